// round 1
// baseline (speedup 1.0000x reference)
#include <cuda_runtime.h>
#include <math.h>

#define NN 50000
#define NE 400000
#define DD 128
#define NG 512

// ------------------- scratch (device globals; no allocation) -------------------
__device__ float g_x[2][NN * DD];            // ping-pong node features
__device__ float g_e[NE * DD];               // edge embeddings
__device__ float g_ABn[NN * 512];            // per-node [AF|BF|AS|BS]
__device__ float g_CC[NE * 256];             // per-edge [CF+bf | CS+bs]
__device__ float g_msg[NN * DD];             // scattered messages
__device__ float g_pooled[NG * DD];
__device__ float g_y[NG * DD];
__device__ float g_t1[NG * 64];
__device__ float g_t2[NG * 32];
__device__ float g_t3[NG * 16];
__device__ float g_Wcat_n[128 * 512];
__device__ float g_Wcat_e[128 * 256];
__device__ float g_bcat_e[256];
__device__ float g_bn[512];                  // [sum | sumsq | scale | shift]

// ------------------- math helpers -------------------
__device__ __forceinline__ float softplusf(float v) {
    return (v > 20.0f) ? v : log1pf(expf(v));
}
__device__ __forceinline__ float sigmoidf(float v) {
    return 1.0f / (1.0f + expf(-v));
}

// ------------------- generic tiled SGEMM: C = act(A[M,K] @ W[K,Ncols] + bias) -------------------
__global__ __launch_bounds__(256) void sgemm(const float* __restrict__ A,
                                             const float* __restrict__ W,
                                             const float* __restrict__ bias,
                                             float* __restrict__ C,
                                             int M, int K, int Ncols, int relu_act)
{
    __shared__ float As[8][128];
    __shared__ float Bs[8][128];
    const int row0 = blockIdx.y * 128;
    const int col0 = blockIdx.x * 128;
    const int tid = threadIdx.x;
    const int tx = tid & 15, ty = tid >> 4;

    float acc[8][8];
#pragma unroll
    for (int m = 0; m < 8; m++)
#pragma unroll
        for (int n = 0; n < 8; n++) acc[m][n] = 0.0f;

    for (int kt = 0; kt < K; kt += 8) {
#pragma unroll
        for (int l = 0; l < 4; l++) {
            int lin = tid + l * 256;
            int ar = lin >> 3, ac = lin & 7;
            int r = row0 + ar, kk = kt + ac;
            As[ac][ar] = (r < M && kk < K) ? A[(size_t)r * K + kk] : 0.0f;
        }
#pragma unroll
        for (int l = 0; l < 4; l++) {
            int lin = tid + l * 256;
            int br = lin >> 7, bc = lin & 127;
            int kk = kt + br;
            Bs[br][bc] = (kk < K) ? W[(size_t)kk * Ncols + col0 + bc] : 0.0f;
        }
        __syncthreads();
#pragma unroll
        for (int kk = 0; kk < 8; kk++) {
            float a[8], b[8];
#pragma unroll
            for (int m = 0; m < 8; m++) a[m] = As[kk][ty * 8 + m];
#pragma unroll
            for (int n = 0; n < 8; n++) b[n] = Bs[kk][tx * 8 + n];
#pragma unroll
            for (int m = 0; m < 8; m++)
#pragma unroll
                for (int n = 0; n < 8; n++) acc[m][n] = fmaf(a[m], b[n], acc[m][n]);
        }
        __syncthreads();
    }

#pragma unroll
    for (int m = 0; m < 8; m++) {
        int r = row0 + ty * 8 + m;
        if (r >= M) continue;
#pragma unroll
        for (int n = 0; n < 8; n++) {
            int c = col0 + tx * 8 + n;
            float v = acc[m][n];
            if (bias) v += bias[c];
            if (relu_act) v = fmaxf(v, 0.0f);
            C[(size_t)r * Ncols + c] = v;
        }
    }
}

// ------------------- small helper kernels -------------------
__global__ void zero_kernel(float* p, int n) {
    int i = blockIdx.x * blockDim.x + threadIdx.x;
    if (i < n) p[i] = 0.0f;
}

// pack node-side weights: Wcat[k][c] for c<128: Wf[k][c], 128..255: Wf[128+k][c-128],
// 256..383: Ws[k][c-256], 384..511: Ws[128+k][c-384]
__global__ void pack_node(const float* __restrict__ Wf, const float* __restrict__ Ws) {
    int idx = blockIdx.x * blockDim.x + threadIdx.x;
    if (idx >= 128 * 512) return;
    int k = idx >> 9, c = idx & 511;
    float v;
    if (c < 128)      v = Wf[k * 128 + c];
    else if (c < 256) v = Wf[(128 + k) * 128 + (c - 128)];
    else if (c < 384) v = Ws[k * 128 + (c - 256)];
    else              v = Ws[(128 + k) * 128 + (c - 384)];
    g_Wcat_n[idx] = v;
}

// pack edge-side weights (bottom 128 rows of Wf/Ws) + biases
__global__ void pack_edge(const float* __restrict__ Wf, const float* __restrict__ Ws,
                          const float* __restrict__ bf, const float* __restrict__ bs) {
    int idx = blockIdx.x * blockDim.x + threadIdx.x;
    if (idx >= 128 * 256) return;
    int k = idx >> 8, c = idx & 255;
    g_Wcat_e[idx] = (c < 128) ? Wf[(256 + k) * 128 + c] : Ws[(256 + k) * 128 + (c - 128)];
    if (idx < 256) g_bcat_e[idx] = (idx < 128) ? bf[idx] : bs[idx - 128];
}

// per-edge gated message + scatter-add by source. 2 edges per 256-thread block.
__global__ __launch_bounds__(256) void edge_kernel(const int* __restrict__ src,
                                                   const int* __restrict__ tgt) {
    int e = blockIdx.x * 2 + (threadIdx.x >> 7);
    if (e >= NE) return;
    int d = threadIdx.x & 127;
    int s = src[e], t = tgt[e];
    const float* rs = g_ABn + (size_t)s * 512;
    const float* rt = g_ABn + (size_t)t * 512;
    const float* ce = g_CC + (size_t)e * 256;
    float f  = rs[d]       + rt[128 + d] + ce[d];
    float sv = rs[256 + d] + rt[384 + d] + ce[128 + d];
    float g = sigmoidf(f) * softplusf(sv);
    atomicAdd(&g_msg[(size_t)s * DD + d], g);
}

// column sums / sumsq over msg (for batch-norm stats)
__global__ void bn_stats() {
    int d = threadIdx.x;
    float s = 0.0f, ss = 0.0f;
    for (int r = blockIdx.x; r < NN; r += gridDim.x) {
        float v = g_msg[(size_t)r * DD + d];
        s += v; ss += v * v;
    }
    atomicAdd(&g_bn[d], s);
    atomicAdd(&g_bn[128 + d], ss);
}

__global__ void bn_finalize(const float* __restrict__ gamma, const float* __restrict__ beta) {
    int d = threadIdx.x;
    float mu  = g_bn[d] * (1.0f / NN);
    float var = g_bn[128 + d] * (1.0f / NN) - mu * mu;
    float rstd = rsqrtf(var + 1e-5f);
    float sc = rstd * gamma[d];
    g_bn[256 + d] = sc;
    g_bn[384 + d] = beta[d] - mu * sc;
}

// x_new = softplus(x + bn(msg));  pooled[batch] += x_new  (batch is sorted -> run-length local acc)
__global__ __launch_bounds__(128) void node_update(const int* __restrict__ batch, int cur) {
    int d = threadIdx.x;
    int r0 = blockIdx.x * 32;
    int rend = min(r0 + 32, NN);
    const float* xin = g_x[cur];
    float* xout = g_x[cur ^ 1];
    float sc = g_bn[256 + d], sh = g_bn[384 + d];
    float acc = 0.0f;
    int curb = batch[r0];
    for (int r = r0; r < rend; r++) {
        int b = batch[r];
        if (b != curb) {
            atomicAdd(&g_pooled[(size_t)curb * DD + d], acc);
            acc = 0.0f; curb = b;
        }
        size_t idx = (size_t)r * DD + d;
        float v = softplusf(xin[idx] + g_msg[idx] * sc + sh);
        xout[idx] = v;
        acc += v;
    }
    atomicAdd(&g_pooled[(size_t)curb * DD + d], acc);
}

// naive small GEMM: C = act((accum? C:0) + A[M,K] @ W[K,Nc] + b)
__global__ void small_gemm(const float* __restrict__ A, const float* __restrict__ W,
                           const float* __restrict__ b, float* __restrict__ C,
                           int M, int K, int Nc, int accum, int act) {
    int idx = blockIdx.x * blockDim.x + threadIdx.x;
    if (idx >= M * Nc) return;
    int r = idx / Nc, c = idx % Nc;
    float s = b[c];
    for (int k = 0; k < K; k++) s = fmaf(A[r * K + k], W[k * Nc + c], s);
    if (accum) s += C[idx];
    if (act) s = fmaxf(s, 0.0f);
    C[idx] = s;
}

// ------------------- host side -------------------
static float* symaddr(const void* sym) {
    void* p = nullptr;
    cudaGetSymbolAddress(&p, sym);
    return (float*)p;
}

extern "C" void kernel_launch(void* const* d_in, const int* in_sizes, int n_in,
                              void* d_out, int out_size)
{
    const float* x_in = (const float*)d_in[0];
    const float* ea   = (const float*)d_in[1];
    const int*   esrc = (const int*)d_in[2];
    const int*   etgt = (const int*)d_in[3];
    const int*   nbat = (const int*)d_in[4];
    const float* Wn   = (const float*)d_in[5];
    const float* bne  = (const float*)d_in[6];
    const float* We   = (const float*)d_in[7];
    const float* bee  = (const float*)d_in[8];
    const float* Wf   = (const float*)d_in[9];
    const float* bf   = (const float*)d_in[10];
    const float* Ws   = (const float*)d_in[11];
    const float* bs   = (const float*)d_in[12];
    // disambiguate dict order (Wg,bg,gamma,beta) vs signature order (gamma,beta,Wg,bg)
    int iWg = 15, ibg = 16, iga = 13, ibe = 14;
    if (in_sizes[13] == 5 * 128 * 128) { iWg = 13; ibg = 14; iga = 15; ibe = 16; }
    const float* Wg    = (const float*)d_in[iWg];
    const float* bg    = (const float*)d_in[ibg];
    const float* gamma = (const float*)d_in[iga];
    const float* beta  = (const float*)d_in[ibe];
    const float* Wr1 = (const float*)d_in[17]; const float* br1 = (const float*)d_in[18];
    const float* Wr2 = (const float*)d_in[19]; const float* br2 = (const float*)d_in[20];
    const float* Wr3 = (const float*)d_in[21]; const float* br3 = (const float*)d_in[22];
    const float* Wr4 = (const float*)d_in[23]; const float* br4 = (const float*)d_in[24];
    float* out = (float*)d_out;

    float* xbuf   = symaddr(g_x);
    float* ebuf   = symaddr(g_e);
    float* abn    = symaddr(g_ABn);
    float* cc     = symaddr(g_CC);
    float* msg    = symaddr(g_msg);
    float* pooled = symaddr(g_pooled);
    float* ybuf   = symaddr(g_y);
    float* t1     = symaddr(g_t1);
    float* t2     = symaddr(g_t2);
    float* t3     = symaddr(g_t3);
    float* wcn    = symaddr(g_Wcat_n);
    float* wce    = symaddr(g_Wcat_e);
    float* bce    = symaddr(g_bcat_e);
    float* bnb    = symaddr(g_bn);

    // embeddings
    { dim3 g(1, (NN + 127) / 128); sgemm<<<g, 256>>>(x_in, Wn, bne, xbuf, NN, 92, 128, 1); }
    { dim3 g(1, (NE + 127) / 128); sgemm<<<g, 256>>>(ea, We, bee, ebuf, NE, 41, 128, 1); }
    zero_kernel<<<(NG * DD + 255) / 256, 256>>>(ybuf, NG * DD);

    int cur = 0;
    for (int i = 0; i < 5; i++) {
        const float* Wfi = Wf + (size_t)i * 384 * 128;
        const float* Wsi = Ws + (size_t)i * 384 * 128;
        pack_node<<<(128 * 512 + 255) / 256, 256>>>(Wfi, Wsi);
        pack_edge<<<(128 * 256 + 255) / 256, 256>>>(Wfi, Wsi, bf + i * 128, bs + i * 128);

        { dim3 g(4, (NN + 127) / 128); sgemm<<<g, 256>>>(xbuf + (size_t)cur * NN * DD, wcn, nullptr, abn, NN, 128, 512, 0); }
        { dim3 g(2, NE / 128);         sgemm<<<g, 256>>>(ebuf, wce, bce, cc, NE, 128, 256, 0); }

        zero_kernel<<<(NN * DD + 255) / 256, 256>>>(msg, NN * DD);
        edge_kernel<<<NE / 2, 256>>>(esrc, etgt);

        zero_kernel<<<1, 256>>>(bnb, 256);
        bn_stats<<<512, 128>>>();
        bn_finalize<<<1, 128>>>(gamma + i * 128, beta + i * 128);

        zero_kernel<<<(NG * DD + 255) / 256, 256>>>(pooled, NG * DD);
        node_update<<<(NN + 31) / 32, 128>>>(nbat, cur);

        small_gemm<<<(NG * 128 + 255) / 256, 256>>>(pooled, Wg + (size_t)i * 128 * 128, bg + i * 128,
                                                    ybuf, NG, 128, 128, 1, 0);
        cur ^= 1;
    }

    small_gemm<<<(NG * 64 + 255) / 256, 256>>>(ybuf, Wr1, br1, t1, NG, 128, 64, 0, 1);
    small_gemm<<<(NG * 32 + 255) / 256, 256>>>(t1, Wr2, br2, t2, NG, 64, 32, 0, 1);
    small_gemm<<<(NG * 16 + 255) / 256, 256>>>(t2, Wr3, br3, t3, NG, 32, 16, 0, 1);
    small_gemm<<<(NG * 1 + 255) / 256, 256>>>(t3, Wr4, br4, out, NG, 16, 1, 0, 1);
}

// round 5
// speedup vs baseline: 2.3534x; 2.3534x over previous
#include <cuda_runtime.h>
#include <math.h>
#include <stdint.h>

#define NN 50000
#define NE 400000
#define DD 128
#define NG 512

#define AS_STRIDE 36
#define BS_STRIDE 136

// ---------------- device scratch ----------------
__device__ float g_x[2][NN * DD];
__device__ float g_e[NE * DD];
__device__ float g_ABn[NN * 512];
__device__ float g_CC[NE * 256];
__device__ float g_msg[NN * DD];
__device__ float g_pooled[NG * DD];
__device__ float g_y[NG * DD];
__device__ float g_t1[NG * 64];
__device__ float g_t2[NG * 32];
__device__ float g_t3[NG * 16];
__device__ float g_Wcat_n[128 * 512];
__device__ float g_Wcat_e[128 * 256];
__device__ float g_bcat_e[256];
__device__ float g_bn[512];

// ---------------- math helpers ----------------
__device__ __forceinline__ float softplusf(float v) {
    return (v > 20.0f) ? v : log1pf(expf(v));
}
__device__ __forceinline__ float sigmoidf(float v) {
    return 1.0f / (1.0f + expf(-v));
}
__device__ __forceinline__ void mma_tf32(float c[4], const uint32_t a[4], const uint32_t b[2]) {
    asm volatile(
        "mma.sync.aligned.m16n8k8.row.col.f32.tf32.tf32.f32 "
        "{%0,%1,%2,%3}, {%4,%5,%6,%7}, {%8,%9}, {%0,%1,%2,%3};"
        : "+f"(c[0]), "+f"(c[1]), "+f"(c[2]), "+f"(c[3])
        : "r"(a[0]), "r"(a[1]), "r"(a[2]), "r"(a[3]), "r"(b[0]), "r"(b[1]));
}

// ---------------- tf32 tensor-core GEMM: C = act(A[M,K] @ W[K,Ncols] + bias) ----------------
// grid: (Ncols/128, ceil(M/128)), 256 threads (8 warps: 4m x 2n). Ncols % 128 == 0.
__global__ __launch_bounds__(256) void mma_gemm(
    const float* __restrict__ A, const float* __restrict__ W,
    const float* __restrict__ bias, float* __restrict__ C,
    int M, int K, int Ncols, int act)
{
    __shared__ float As[128 * AS_STRIDE];   // 18432 B
    __shared__ float Bs[32 * BS_STRIDE];    // 17408 B
    const int tid = threadIdx.x;
    const int lane = tid & 31, wid = tid >> 5;
    const int warp_m = wid & 3, warp_n = wid >> 2;
    const int row0 = blockIdx.y * 128;
    const int col0 = blockIdx.x * 128;
    const int mr = lane >> 2, kc = lane & 3;

    float c[2][8][4];
#pragma unroll
    for (int i = 0; i < 2; i++)
#pragma unroll
        for (int j = 0; j < 8; j++)
#pragma unroll
            for (int q = 0; q < 4; q++) c[i][j][q] = 0.0f;

    const int nchunks = (K + 31) >> 5;
    const bool vec = (K & 31) == 0;

    for (int ch = 0; ch < nchunks; ch++) {
        int k0 = ch << 5;
        if (vec) {
            // float4 fills: A 128 rows x 32 cols, B 32 rows x 128 cols
#pragma unroll
            for (int i = 0; i < 4; i++) {
                int lin = tid + i * 256;
                int r = lin >> 3, kv = (lin & 7) << 2;
                int gr = row0 + r;
                float4 v = make_float4(0.f, 0.f, 0.f, 0.f);
                if (gr < M) v = *(const float4*)(A + (size_t)gr * K + k0 + kv);
                As[r * AS_STRIDE + kv + 0] = v.x;
                As[r * AS_STRIDE + kv + 1] = v.y;
                As[r * AS_STRIDE + kv + 2] = v.z;
                As[r * AS_STRIDE + kv + 3] = v.w;
            }
#pragma unroll
            for (int i = 0; i < 4; i++) {
                int lin = tid + i * 256;
                int r = lin >> 5, nv = (lin & 31) << 2;
                float4 v = *(const float4*)(W + (size_t)(k0 + r) * Ncols + col0 + nv);
                Bs[r * BS_STRIDE + nv + 0] = v.x;
                Bs[r * BS_STRIDE + nv + 1] = v.y;
                Bs[r * BS_STRIDE + nv + 2] = v.z;
                Bs[r * BS_STRIDE + nv + 3] = v.w;
            }
        } else {
            // scalar fills with bounds (embeddings: K=92/41)
#pragma unroll 4
            for (int lin = tid; lin < 128 * 32; lin += 256) {
                int r = lin >> 5, k = lin & 31;
                int gr = row0 + r, gk = k0 + k;
                As[r * AS_STRIDE + k] = (gr < M && gk < K) ? A[(size_t)gr * K + gk] : 0.0f;
            }
#pragma unroll 4
            for (int lin = tid; lin < 32 * 128; lin += 256) {
                int r = lin >> 7, n = lin & 127;
                int gk = k0 + r;
                Bs[r * BS_STRIDE + n] = (gk < K) ? W[(size_t)gk * Ncols + col0 + n] : 0.0f;
            }
        }
        __syncthreads();

#pragma unroll
        for (int ks = 0; ks < 4; ks++) {
            int k = ks << 3;
            uint32_t a[2][4], b[8][2];
#pragma unroll
            for (int fm = 0; fm < 2; fm++) {
                int mb = warp_m * 32 + fm * 16 + mr;
                a[fm][0] = __float_as_uint(As[mb * AS_STRIDE + k + kc]);
                a[fm][1] = __float_as_uint(As[(mb + 8) * AS_STRIDE + k + kc]);
                a[fm][2] = __float_as_uint(As[mb * AS_STRIDE + k + kc + 4]);
                a[fm][3] = __float_as_uint(As[(mb + 8) * AS_STRIDE + k + kc + 4]);
            }
#pragma unroll
            for (int fn = 0; fn < 8; fn++) {
                int nb = warp_n * 64 + fn * 8 + mr;
                b[fn][0] = __float_as_uint(Bs[(k + kc) * BS_STRIDE + nb]);
                b[fn][1] = __float_as_uint(Bs[(k + kc + 4) * BS_STRIDE + nb]);
            }
#pragma unroll
            for (int fm = 0; fm < 2; fm++)
#pragma unroll
                for (int fn = 0; fn < 8; fn++) mma_tf32(c[fm][fn], a[fm], b[fn]);
        }
        __syncthreads();
    }

    // ---- epilogue ----
#pragma unroll
    for (int fm = 0; fm < 2; fm++) {
        int rr = row0 + warp_m * 32 + fm * 16 + mr;
#pragma unroll
        for (int fn = 0; fn < 8; fn++) {
            int cc = col0 + warp_n * 64 + fn * 8 + kc * 2;
            float b0 = 0.0f, b1 = 0.0f;
            if (bias) { b0 = bias[cc]; b1 = bias[cc + 1]; }
            float v0 = c[fm][fn][0] + b0, v1 = c[fm][fn][1] + b1;
            float v2 = c[fm][fn][2] + b0, v3 = c[fm][fn][3] + b1;
            if (act) {
                v0 = fmaxf(v0, 0.0f); v1 = fmaxf(v1, 0.0f);
                v2 = fmaxf(v2, 0.0f); v3 = fmaxf(v3, 0.0f);
            }
            if (rr < M) *(float2*)&C[(size_t)rr * Ncols + cc] = make_float2(v0, v1);
            if (rr + 8 < M) *(float2*)&C[(size_t)(rr + 8) * Ncols + cc] = make_float2(v2, v3);
        }
    }
}

// ---------------- non-GEMM kernels (identical to passing R1) ----------------
__global__ void zero_kernel(float* p, int n) {
    int i = blockIdx.x * blockDim.x + threadIdx.x;
    if (i < n) p[i] = 0.0f;
}

__global__ void pack_node(const float* __restrict__ Wf, const float* __restrict__ Ws) {
    int idx = blockIdx.x * blockDim.x + threadIdx.x;
    if (idx >= 128 * 512) return;
    int k = idx >> 9, c = idx & 511;
    float v;
    if (c < 128)      v = Wf[k * 128 + c];
    else if (c < 256) v = Wf[(128 + k) * 128 + (c - 128)];
    else if (c < 384) v = Ws[k * 128 + (c - 256)];
    else              v = Ws[(128 + k) * 128 + (c - 384)];
    g_Wcat_n[idx] = v;
}

__global__ void pack_edge(const float* __restrict__ Wf, const float* __restrict__ Ws,
                          const float* __restrict__ bf, const float* __restrict__ bs) {
    int idx = blockIdx.x * blockDim.x + threadIdx.x;
    if (idx >= 128 * 256) return;
    int k = idx >> 8, c = idx & 255;
    g_Wcat_e[idx] = (c < 128) ? Wf[(256 + k) * 128 + c] : Ws[(256 + k) * 128 + (c - 128)];
    if (idx < 256) g_bcat_e[idx] = (idx < 128) ? bf[idx] : bs[idx - 128];
}

__global__ __launch_bounds__(256) void edge_kernel(const int* __restrict__ src,
                                                   const int* __restrict__ tgt) {
    int e = blockIdx.x * 2 + (threadIdx.x >> 7);
    if (e >= NE) return;
    int d = threadIdx.x & 127;
    int s = src[e], t = tgt[e];
    const float* rs = g_ABn + (size_t)s * 512;
    const float* rt = g_ABn + (size_t)t * 512;
    const float* ce = g_CC + (size_t)e * 256;
    float f  = rs[d]       + rt[128 + d] + ce[d];
    float sv = rs[256 + d] + rt[384 + d] + ce[128 + d];
    float g = sigmoidf(f) * softplusf(sv);
    atomicAdd(&g_msg[(size_t)s * DD + d], g);
}

__global__ void bn_stats() {
    int d = threadIdx.x;
    float s = 0.0f, ss = 0.0f;
    for (int r = blockIdx.x; r < NN; r += gridDim.x) {
        float v = g_msg[(size_t)r * DD + d];
        s += v; ss += v * v;
    }
    atomicAdd(&g_bn[d], s);
    atomicAdd(&g_bn[128 + d], ss);
}

__global__ void bn_finalize(const float* __restrict__ gamma, const float* __restrict__ beta) {
    int d = threadIdx.x;
    float mu  = g_bn[d] * (1.0f / NN);
    float var = g_bn[128 + d] * (1.0f / NN) - mu * mu;
    float rstd = rsqrtf(var + 1e-5f);
    float sc = rstd * gamma[d];
    g_bn[256 + d] = sc;
    g_bn[384 + d] = beta[d] - mu * sc;
}

__global__ __launch_bounds__(128) void node_update(const int* __restrict__ batch, int cur) {
    int d = threadIdx.x;
    int r0 = blockIdx.x * 32;
    int rend = min(r0 + 32, NN);
    const float* xin = g_x[cur];
    float* xout = g_x[cur ^ 1];
    float sc = g_bn[256 + d], sh = g_bn[384 + d];
    float acc = 0.0f;
    int curb = batch[r0];
    for (int r = r0; r < rend; r++) {
        int b = batch[r];
        if (b != curb) {
            atomicAdd(&g_pooled[(size_t)curb * DD + d], acc);
            acc = 0.0f; curb = b;
        }
        size_t idx = (size_t)r * DD + d;
        float v = softplusf(xin[idx] + g_msg[idx] * sc + sh);
        xout[idx] = v;
        acc += v;
    }
    atomicAdd(&g_pooled[(size_t)curb * DD + d], acc);
}

__global__ void small_gemm(const float* __restrict__ A, const float* __restrict__ W,
                           const float* __restrict__ b, float* __restrict__ C,
                           int M, int K, int Nc, int accum, int act) {
    int idx = blockIdx.x * blockDim.x + threadIdx.x;
    if (idx >= M * Nc) return;
    int r = idx / Nc, c = idx % Nc;
    float s = b[c];
    for (int k = 0; k < K; k++) s = fmaf(A[r * K + k], W[k * Nc + c], s);
    if (accum) s += C[idx];
    if (act) s = fmaxf(s, 0.0f);
    C[idx] = s;
}

// ---------------- host ----------------
static float* symaddr(const void* sym) {
    void* p = nullptr;
    cudaGetSymbolAddress(&p, sym);
    return (float*)p;
}

extern "C" void kernel_launch(void* const* d_in, const int* in_sizes, int n_in,
                              void* d_out, int out_size)
{
    const float* x_in = (const float*)d_in[0];
    const float* ea   = (const float*)d_in[1];
    const int*   esrc = (const int*)d_in[2];
    const int*   etgt = (const int*)d_in[3];
    const int*   nbat = (const int*)d_in[4];
    const float* Wn   = (const float*)d_in[5];
    const float* bne  = (const float*)d_in[6];
    const float* We   = (const float*)d_in[7];
    const float* bee  = (const float*)d_in[8];
    const float* Wf   = (const float*)d_in[9];
    const float* bf   = (const float*)d_in[10];
    const float* Ws   = (const float*)d_in[11];
    const float* bs   = (const float*)d_in[12];
    int iWg = 15, ibg = 16, iga = 13, ibe = 14;
    if (in_sizes[13] == 5 * 128 * 128) { iWg = 13; ibg = 14; iga = 15; ibe = 16; }
    const float* Wg    = (const float*)d_in[iWg];
    const float* bg    = (const float*)d_in[ibg];
    const float* gamma = (const float*)d_in[iga];
    const float* beta  = (const float*)d_in[ibe];
    const float* Wr1 = (const float*)d_in[17]; const float* br1 = (const float*)d_in[18];
    const float* Wr2 = (const float*)d_in[19]; const float* br2 = (const float*)d_in[20];
    const float* Wr3 = (const float*)d_in[21]; const float* br3 = (const float*)d_in[22];
    const float* Wr4 = (const float*)d_in[23]; const float* br4 = (const float*)d_in[24];
    float* out = (float*)d_out;

    float* xbuf   = symaddr(g_x);
    float* ebuf   = symaddr(g_e);
    float* abn    = symaddr(g_ABn);
    float* cc     = symaddr(g_CC);
    float* msg    = symaddr(g_msg);
    float* pooled = symaddr(g_pooled);
    float* ybuf   = symaddr(g_y);
    float* t1     = symaddr(g_t1);
    float* t2     = symaddr(g_t2);
    float* t3     = symaddr(g_t3);
    float* wcn    = symaddr(g_Wcat_n);
    float* wce    = symaddr(g_Wcat_e);
    float* bce    = symaddr(g_bcat_e);
    float* bnb    = symaddr(g_bn);

    // embeddings (tensor-core, scalar-load path for odd K)
    mma_gemm<<<dim3(1, (NN + 127) / 128), 256>>>(x_in, Wn, bne, xbuf, NN, 92, 128, 1);
    mma_gemm<<<dim3(1, (NE + 127) / 128), 256>>>(ea, We, bee, ebuf, NE, 41, 128, 1);
    zero_kernel<<<(NG * DD + 255) / 256, 256>>>(ybuf, NG * DD);

    int cur = 0;
    for (int i = 0; i < 5; i++) {
        const float* Wfi = Wf + (size_t)i * 384 * 128;
        const float* Wsi = Ws + (size_t)i * 384 * 128;
        pack_node<<<(128 * 512 + 255) / 256, 256>>>(Wfi, Wsi);
        pack_edge<<<(128 * 256 + 255) / 256, 256>>>(Wfi, Wsi, bf + i * 128, bs + i * 128);

        mma_gemm<<<dim3(4, (NN + 127) / 128), 256>>>(
            xbuf + (size_t)cur * NN * DD, wcn, nullptr, abn, NN, 128, 512, 0);
        mma_gemm<<<dim3(2, NE / 128), 256>>>(
            ebuf, wce, bce, cc, NE, 128, 256, 0);

        zero_kernel<<<(NN * DD + 255) / 256, 256>>>(msg, NN * DD);
        edge_kernel<<<NE / 2, 256>>>(esrc, etgt);

        zero_kernel<<<1, 256>>>(bnb, 256);
        bn_stats<<<512, 128>>>();
        bn_finalize<<<1, 128>>>(gamma + i * 128, beta + i * 128);

        zero_kernel<<<(NG * DD + 255) / 256, 256>>>(pooled, NG * DD);
        node_update<<<(NN + 31) / 32, 128>>>(nbat, cur);

        small_gemm<<<(NG * 128 + 255) / 256, 256>>>(pooled, Wg + (size_t)i * 128 * 128,
                                                    bg + i * 128, ybuf, NG, 128, 128, 1, 0);
        cur ^= 1;
    }

    small_gemm<<<(NG * 64 + 255) / 256, 256>>>(ybuf, Wr1, br1, t1, NG, 128, 64, 0, 1);
    small_gemm<<<(NG * 32 + 255) / 256, 256>>>(t1, Wr2, br2, t2, NG, 64, 32, 0, 1);
    small_gemm<<<(NG * 16 + 255) / 256, 256>>>(t2, Wr3, br3, t3, NG, 32, 16, 0, 1);
    small_gemm<<<(NG * 1 + 255) / 256, 256>>>(t3, Wr4, br4, out, NG, 16, 1, 0, 1);
}

// round 6
// speedup vs baseline: 2.6996x; 1.1471x over previous
#include <cuda_runtime.h>
#include <math.h>
#include <stdint.h>

#define NN 50000
#define NE 400000
#define DD 128
#define NG 512

#define AS_STRIDE 36
#define BS_STRIDE 136

// ---------------- device scratch ----------------
__device__ __align__(16) float g_x[2][NN * DD];
__device__ __align__(16) float g_e[NE * DD];
__device__ __align__(16) float g_ABn[NN * 512];   // interleaved [AF0,AS0,...|BF0,BS0,...]
__device__ __align__(16) float g_msg[NN * DD];
__device__ __align__(16) float g_pooled[NG * DD];
__device__ __align__(16) float g_y[NG * DD];
__device__ __align__(16) float g_t1[NG * 64];
__device__ __align__(16) float g_t2[NG * 32];
__device__ __align__(16) float g_t3[NG * 16];
__device__ __align__(16) float g_Wcat_n[128 * 512];  // interleaved cols
__device__ __align__(16) float g_Wcat_e[128 * 256];  // interleaved cols
__device__ __align__(16) float g_bcat_e[256];        // interleaved bias
__device__ __align__(16) float g_bn[512];

// ---------------- math helpers ----------------
__device__ __forceinline__ float fsp(float v) {        // softplus
    return (v > 20.0f) ? v : __logf(1.0f + __expf(v));
}
__device__ __forceinline__ float fsig(float v) {       // sigmoid
    return __fdividef(1.0f, 1.0f + __expf(-v));
}
__device__ __forceinline__ void mma_tf32(float c[4], const uint32_t a[4], const uint32_t b[2]) {
    asm volatile(
        "mma.sync.aligned.m16n8k8.row.col.f32.tf32.tf32.f32 "
        "{%0,%1,%2,%3}, {%4,%5,%6,%7}, {%8,%9}, {%0,%1,%2,%3};"
        : "+f"(c[0]), "+f"(c[1]), "+f"(c[2]), "+f"(c[3])
        : "r"(a[0]), "r"(a[1]), "r"(a[2]), "r"(a[3]), "r"(b[0]), "r"(b[1]));
}

// ---------------- generic tf32 GEMM: C = act(A[M,K] @ W[K,Ncols] + bias) ----------------
// grid: (Ncols/128, ceil(M/128)), 256 threads (8 warps: 4m x 2n).
__global__ __launch_bounds__(256) void mma_gemm(
    const float* __restrict__ A, const float* __restrict__ W,
    const float* __restrict__ bias, float* __restrict__ C,
    int M, int K, int Ncols, int act)
{
    __shared__ float As[128 * AS_STRIDE];
    __shared__ float Bs[32 * BS_STRIDE];
    const int tid = threadIdx.x;
    const int lane = tid & 31, wid = tid >> 5;
    const int warp_m = wid & 3, warp_n = wid >> 2;
    const int row0 = blockIdx.y * 128;
    const int col0 = blockIdx.x * 128;
    const int mr = lane >> 2, kc = lane & 3;

    float c[2][8][4];
#pragma unroll
    for (int i = 0; i < 2; i++)
#pragma unroll
        for (int j = 0; j < 8; j++)
#pragma unroll
            for (int q = 0; q < 4; q++) c[i][j][q] = 0.0f;

    const int nchunks = (K + 31) >> 5;
    const bool vec = (K & 31) == 0;

    for (int ch = 0; ch < nchunks; ch++) {
        int k0 = ch << 5;
        if (vec) {
#pragma unroll
            for (int i = 0; i < 4; i++) {
                int lin = tid + i * 256;
                int r = lin >> 3, kv = (lin & 7) << 2;
                int gr = row0 + r;
                float4 v = make_float4(0.f, 0.f, 0.f, 0.f);
                if (gr < M) v = *(const float4*)(A + (size_t)gr * K + k0 + kv);
                As[r * AS_STRIDE + kv + 0] = v.x;
                As[r * AS_STRIDE + kv + 1] = v.y;
                As[r * AS_STRIDE + kv + 2] = v.z;
                As[r * AS_STRIDE + kv + 3] = v.w;
            }
#pragma unroll
            for (int i = 0; i < 4; i++) {
                int lin = tid + i * 256;
                int r = lin >> 5, nv = (lin & 31) << 2;
                float4 v = *(const float4*)(W + (size_t)(k0 + r) * Ncols + col0 + nv);
                Bs[r * BS_STRIDE + nv + 0] = v.x;
                Bs[r * BS_STRIDE + nv + 1] = v.y;
                Bs[r * BS_STRIDE + nv + 2] = v.z;
                Bs[r * BS_STRIDE + nv + 3] = v.w;
            }
        } else {
#pragma unroll 4
            for (int lin = tid; lin < 128 * 32; lin += 256) {
                int r = lin >> 5, k = lin & 31;
                int gr = row0 + r, gk = k0 + k;
                As[r * AS_STRIDE + k] = (gr < M && gk < K) ? A[(size_t)gr * K + gk] : 0.0f;
            }
#pragma unroll 4
            for (int lin = tid; lin < 32 * 128; lin += 256) {
                int r = lin >> 7, n = lin & 127;
                int gk = k0 + r;
                Bs[r * BS_STRIDE + n] = (gk < K) ? W[(size_t)gk * Ncols + col0 + n] : 0.0f;
            }
        }
        __syncthreads();

#pragma unroll
        for (int ks = 0; ks < 4; ks++) {
            int k = ks << 3;
            uint32_t a[2][4], b[8][2];
#pragma unroll
            for (int fm = 0; fm < 2; fm++) {
                int mb = warp_m * 32 + fm * 16 + mr;
                a[fm][0] = __float_as_uint(As[mb * AS_STRIDE + k + kc]);
                a[fm][1] = __float_as_uint(As[(mb + 8) * AS_STRIDE + k + kc]);
                a[fm][2] = __float_as_uint(As[mb * AS_STRIDE + k + kc + 4]);
                a[fm][3] = __float_as_uint(As[(mb + 8) * AS_STRIDE + k + kc + 4]);
            }
#pragma unroll
            for (int fn = 0; fn < 8; fn++) {
                int nb = warp_n * 64 + fn * 8 + mr;
                b[fn][0] = __float_as_uint(Bs[(k + kc) * BS_STRIDE + nb]);
                b[fn][1] = __float_as_uint(Bs[(k + kc + 4) * BS_STRIDE + nb]);
            }
#pragma unroll
            for (int fm = 0; fm < 2; fm++)
#pragma unroll
                for (int fn = 0; fn < 8; fn++) mma_tf32(c[fm][fn], a[fm], b[fn]);
        }
        __syncthreads();
    }

#pragma unroll
    for (int fm = 0; fm < 2; fm++) {
        int rr = row0 + warp_m * 32 + fm * 16 + mr;
#pragma unroll
        for (int fn = 0; fn < 8; fn++) {
            int cc = col0 + warp_n * 64 + fn * 8 + kc * 2;
            float b0 = 0.0f, b1 = 0.0f;
            if (bias) { b0 = bias[cc]; b1 = bias[cc + 1]; }
            float v0 = c[fm][fn][0] + b0, v1 = c[fm][fn][1] + b1;
            float v2 = c[fm][fn][2] + b0, v3 = c[fm][fn][3] + b1;
            if (act) {
                v0 = fmaxf(v0, 0.0f); v1 = fmaxf(v1, 0.0f);
                v2 = fmaxf(v2, 0.0f); v3 = fmaxf(v3, 0.0f);
            }
            if (rr < M) *(float2*)&C[(size_t)rr * Ncols + cc] = make_float2(v0, v1);
            if (rr + 8 < M) *(float2*)&C[(size_t)(rr + 8) * Ncols + cc] = make_float2(v2, v3);
        }
    }
}

// ---------------- fused edge GEMM + gating + scatter ----------------
// A = g_e [NE,128], W = g_Wcat_e [128,256] interleaved (f,s) pairs.
// grid: (2, NE/128). Epilogue: g = sigmoid(f)*softplus(s) -> atomicAdd msg[src][d].
__global__ __launch_bounds__(256) void edge_fused(const int* __restrict__ src,
                                                  const int* __restrict__ tgt)
{
    __shared__ float As[128 * AS_STRIDE];
    __shared__ float Bs[32 * BS_STRIDE];
    const int tid = threadIdx.x;
    const int lane = tid & 31, wid = tid >> 5;
    const int warp_m = wid & 3, warp_n = wid >> 2;
    const int row0 = blockIdx.y * 128;       // edge base (NE % 128 == 0)
    const int col0 = blockIdx.x * 128;       // 0 or 128 of 256 interleaved cols
    const int mr = lane >> 2, kc = lane & 3;

    float c[2][8][4];
#pragma unroll
    for (int i = 0; i < 2; i++)
#pragma unroll
        for (int j = 0; j < 8; j++)
#pragma unroll
            for (int q = 0; q < 4; q++) c[i][j][q] = 0.0f;

#pragma unroll 1
    for (int ch = 0; ch < 4; ch++) {
        int k0 = ch << 5;
#pragma unroll
        for (int i = 0; i < 4; i++) {
            int lin = tid + i * 256;
            int r = lin >> 3, kv = (lin & 7) << 2;
            float4 v = *(const float4*)(g_e + (size_t)(row0 + r) * 128 + k0 + kv);
            As[r * AS_STRIDE + kv + 0] = v.x;
            As[r * AS_STRIDE + kv + 1] = v.y;
            As[r * AS_STRIDE + kv + 2] = v.z;
            As[r * AS_STRIDE + kv + 3] = v.w;
        }
#pragma unroll
        for (int i = 0; i < 4; i++) {
            int lin = tid + i * 256;
            int r = lin >> 5, nv = (lin & 31) << 2;
            float4 v = *(const float4*)(g_Wcat_e + (size_t)(k0 + r) * 256 + col0 + nv);
            Bs[r * BS_STRIDE + nv + 0] = v.x;
            Bs[r * BS_STRIDE + nv + 1] = v.y;
            Bs[r * BS_STRIDE + nv + 2] = v.z;
            Bs[r * BS_STRIDE + nv + 3] = v.w;
        }
        __syncthreads();

#pragma unroll
        for (int ks = 0; ks < 4; ks++) {
            int k = ks << 3;
            uint32_t a[2][4], b[8][2];
#pragma unroll
            for (int fm = 0; fm < 2; fm++) {
                int mb = warp_m * 32 + fm * 16 + mr;
                a[fm][0] = __float_as_uint(As[mb * AS_STRIDE + k + kc]);
                a[fm][1] = __float_as_uint(As[(mb + 8) * AS_STRIDE + k + kc]);
                a[fm][2] = __float_as_uint(As[mb * AS_STRIDE + k + kc + 4]);
                a[fm][3] = __float_as_uint(As[(mb + 8) * AS_STRIDE + k + kc + 4]);
            }
#pragma unroll
            for (int fn = 0; fn < 8; fn++) {
                int nb = warp_n * 64 + fn * 8 + mr;
                b[fn][0] = __float_as_uint(Bs[(k + kc) * BS_STRIDE + nb]);
                b[fn][1] = __float_as_uint(Bs[(k + kc + 4) * BS_STRIDE + nb]);
            }
#pragma unroll
            for (int fm = 0; fm < 2; fm++)
#pragma unroll
                for (int fn = 0; fn < 8; fn++) mma_tf32(c[fm][fn], a[fm], b[fn]);
        }
        __syncthreads();
    }

    // ---- fused epilogue: gate + scatter ----
#pragma unroll
    for (int fm = 0; fm < 2; fm++) {
        int e1 = row0 + warp_m * 32 + fm * 16 + mr;
        int e2 = e1 + 8;
        int s1 = src[e1], t1 = tgt[e1];
        int s2 = src[e2], t2 = tgt[e2];
        const float2* sa1 = (const float2*)(g_ABn + (size_t)s1 * 512);
        const float2* ta1 = (const float2*)(g_ABn + (size_t)t1 * 512 + 256);
        const float2* sa2 = (const float2*)(g_ABn + (size_t)s2 * 512);
        const float2* ta2 = (const float2*)(g_ABn + (size_t)t2 * 512 + 256);
        float* m1 = g_msg + (size_t)s1 * DD;
        float* m2 = g_msg + (size_t)s2 * DD;
#pragma unroll
        for (int fn = 0; fn < 8; fn++) {
            int cc = col0 + warp_n * 64 + fn * 8 + kc * 2;
            int d = cc >> 1;
            float2 bi = *(const float2*)&g_bcat_e[cc];
            float2 u1 = sa1[d], v1 = ta1[d];
            float f1 = c[fm][fn][0] + bi.x + u1.x + v1.x;
            float w1 = c[fm][fn][1] + bi.y + u1.y + v1.y;
            atomicAdd(&m1[d], fsig(f1) * fsp(w1));
            float2 u2 = sa2[d], v2 = ta2[d];
            float f2 = c[fm][fn][2] + bi.x + u2.x + v2.x;
            float w2 = c[fm][fn][3] + bi.y + u2.y + v2.y;
            atomicAdd(&m2[d], fsig(f2) * fsp(w2));
        }
    }
}

// ---------------- small kernels ----------------
__global__ void zero_kernel(float* p, int n) {
    int i = blockIdx.x * blockDim.x + threadIdx.x;
    if (i < n) p[i] = 0.0f;
}

// interleaved node pack: c<256: (d=c>>1, f/s) from rows k / top-blocks; c>=256 from rows 128+k
__global__ void pack_node(const float* __restrict__ Wf, const float* __restrict__ Ws) {
    int idx = blockIdx.x * blockDim.x + threadIdx.x;
    if (idx >= 128 * 512) return;
    int k = idx >> 9, c = idx & 511;
    float v;
    if (c < 256) {
        int d = c >> 1;
        v = (c & 1) ? Ws[k * 128 + d] : Wf[k * 128 + d];
    } else {
        int d = (c - 256) >> 1;
        v = (c & 1) ? Ws[(128 + k) * 128 + d] : Wf[(128 + k) * 128 + d];
    }
    g_Wcat_n[idx] = v;
}

__global__ void pack_edge(const float* __restrict__ Wf, const float* __restrict__ Ws,
                          const float* __restrict__ bf, const float* __restrict__ bs) {
    int idx = blockIdx.x * blockDim.x + threadIdx.x;
    if (idx >= 128 * 256) return;
    int k = idx >> 8, c = idx & 255;
    int d = c >> 1;
    g_Wcat_e[idx] = (c & 1) ? Ws[(256 + k) * 128 + d] : Wf[(256 + k) * 128 + d];
    if (idx < 256) g_bcat_e[idx] = (idx & 1) ? bs[idx >> 1] : bf[idx >> 1];
}

__global__ void bn_stats() {
    int d = threadIdx.x;
    float s = 0.0f, ss = 0.0f;
    for (int r = blockIdx.x; r < NN; r += gridDim.x) {
        float v = g_msg[(size_t)r * DD + d];
        s += v; ss += v * v;
    }
    atomicAdd(&g_bn[d], s);
    atomicAdd(&g_bn[128 + d], ss);
}

__global__ void bn_finalize(const float* __restrict__ gamma, const float* __restrict__ beta) {
    int d = threadIdx.x;
    float mu  = g_bn[d] * (1.0f / NN);
    float var = g_bn[128 + d] * (1.0f / NN) - mu * mu;
    float rstd = rsqrtf(var + 1e-5f);
    float sc = rstd * gamma[d];
    g_bn[256 + d] = sc;
    g_bn[384 + d] = beta[d] - mu * sc;
}

__global__ __launch_bounds__(128) void node_update(const int* __restrict__ batch, int cur) {
    int d = threadIdx.x;
    int r0 = blockIdx.x * 32;
    int rend = min(r0 + 32, NN);
    const float* xin = g_x[cur];
    float* xout = g_x[cur ^ 1];
    float sc = g_bn[256 + d], sh = g_bn[384 + d];
    float acc = 0.0f;
    int curb = batch[r0];
    for (int r = r0; r < rend; r++) {
        int b = batch[r];
        if (b != curb) {
            atomicAdd(&g_pooled[(size_t)curb * DD + d], acc);
            acc = 0.0f; curb = b;
        }
        size_t idx = (size_t)r * DD + d;
        float v = fsp(xin[idx] + g_msg[idx] * sc + sh);
        xout[idx] = v;
        acc += v;
    }
    atomicAdd(&g_pooled[(size_t)curb * DD + d], acc);
}

__global__ void small_gemm(const float* __restrict__ A, const float* __restrict__ W,
                           const float* __restrict__ b, float* __restrict__ C,
                           int M, int K, int Nc, int accum, int act) {
    int idx = blockIdx.x * blockDim.x + threadIdx.x;
    if (idx >= M * Nc) return;
    int r = idx / Nc, c = idx % Nc;
    float s = b[c];
    for (int k = 0; k < K; k++) s = fmaf(A[r * K + k], W[k * Nc + c], s);
    if (accum) s += C[idx];
    if (act) s = fmaxf(s, 0.0f);
    C[idx] = s;
}

// ---------------- host ----------------
static float* symaddr(const void* sym) {
    void* p = nullptr;
    cudaGetSymbolAddress(&p, sym);
    return (float*)p;
}

extern "C" void kernel_launch(void* const* d_in, const int* in_sizes, int n_in,
                              void* d_out, int out_size)
{
    const float* x_in = (const float*)d_in[0];
    const float* ea   = (const float*)d_in[1];
    const int*   esrc = (const int*)d_in[2];
    const int*   etgt = (const int*)d_in[3];
    const int*   nbat = (const int*)d_in[4];
    const float* Wn   = (const float*)d_in[5];
    const float* bne  = (const float*)d_in[6];
    const float* We   = (const float*)d_in[7];
    const float* bee  = (const float*)d_in[8];
    const float* Wf   = (const float*)d_in[9];
    const float* bf   = (const float*)d_in[10];
    const float* Ws   = (const float*)d_in[11];
    const float* bs   = (const float*)d_in[12];
    int iWg = 15, ibg = 16, iga = 13, ibe = 14;
    if (in_sizes[13] == 5 * 128 * 128) { iWg = 13; ibg = 14; iga = 15; ibe = 16; }
    const float* Wg    = (const float*)d_in[iWg];
    const float* bg    = (const float*)d_in[ibg];
    const float* gamma = (const float*)d_in[iga];
    const float* beta  = (const float*)d_in[ibe];
    const float* Wr1 = (const float*)d_in[17]; const float* br1 = (const float*)d_in[18];
    const float* Wr2 = (const float*)d_in[19]; const float* br2 = (const float*)d_in[20];
    const float* Wr3 = (const float*)d_in[21]; const float* br3 = (const float*)d_in[22];
    const float* Wr4 = (const float*)d_in[23]; const float* br4 = (const float*)d_in[24];
    float* out = (float*)d_out;

    float* xbuf   = symaddr(g_x);
    float* ebuf   = symaddr(g_e);
    float* abn    = symaddr(g_ABn);
    float* msg    = symaddr(g_msg);
    float* pooled = symaddr(g_pooled);
    float* ybuf   = symaddr(g_y);
    float* t1     = symaddr(g_t1);
    float* t2     = symaddr(g_t2);
    float* t3     = symaddr(g_t3);
    float* wcn    = symaddr(g_Wcat_n);
    float* bnb    = symaddr(g_bn);

    // embeddings (tensor-core, scalar-load path for odd K)
    mma_gemm<<<dim3(1, (NN + 127) / 128), 256>>>(x_in, Wn, bne, xbuf, NN, 92, 128, 1);
    mma_gemm<<<dim3(1, (NE + 127) / 128), 256>>>(ea, We, bee, ebuf, NE, 41, 128, 1);
    zero_kernel<<<(NG * DD + 255) / 256, 256>>>(ybuf, NG * DD);

    int cur = 0;
    for (int i = 0; i < 5; i++) {
        const float* Wfi = Wf + (size_t)i * 384 * 128;
        const float* Wsi = Ws + (size_t)i * 384 * 128;
        pack_node<<<(128 * 512 + 255) / 256, 256>>>(Wfi, Wsi);
        pack_edge<<<(128 * 256 + 255) / 256, 256>>>(Wfi, Wsi, bf + i * 128, bs + i * 128);

        mma_gemm<<<dim3(4, (NN + 127) / 128), 256>>>(
            xbuf + (size_t)cur * NN * DD, wcn, nullptr, abn, NN, 128, 512, 0);

        zero_kernel<<<(NN * DD + 255) / 256, 256>>>(msg, NN * DD);
        edge_fused<<<dim3(2, NE / 128), 256>>>(esrc, etgt);

        zero_kernel<<<1, 256>>>(bnb, 256);
        bn_stats<<<512, 128>>>();
        bn_finalize<<<1, 128>>>(gamma + i * 128, beta + i * 128);

        zero_kernel<<<(NG * DD + 255) / 256, 256>>>(pooled, NG * DD);
        node_update<<<(NN + 31) / 32, 128>>>(nbat, cur);

        small_gemm<<<(NG * 128 + 255) / 256, 256>>>(pooled, Wg + (size_t)i * 128 * 128,
                                                    bg + i * 128, ybuf, NG, 128, 128, 1, 0);
        cur ^= 1;
    }

    small_gemm<<<(NG * 64 + 255) / 256, 256>>>(ybuf, Wr1, br1, t1, NG, 128, 64, 0, 1);
    small_gemm<<<(NG * 32 + 255) / 256, 256>>>(t1, Wr2, br2, t2, NG, 64, 32, 0, 1);
    small_gemm<<<(NG * 16 + 255) / 256, 256>>>(t2, Wr3, br3, t3, NG, 32, 16, 0, 1);
    small_gemm<<<(NG * 1 + 255) / 256, 256>>>(t3, Wr4, br4, out, NG, 16, 1, 0, 1);
}

// round 8
// speedup vs baseline: 2.8335x; 1.0496x over previous
#include <cuda_runtime.h>
#include <math.h>
#include <stdint.h>

#define NN 50000
#define NE 400000
#define DD 128
#define NG 512

#define AS_STRIDE 36
#define BS_STRIDE 136

// ---------------- device scratch ----------------
__device__ __align__(16) float g_x[2][NN * DD];
__device__ __align__(16) float g_e[NE * DD];
__device__ __align__(16) float g_ABn[NN * 512];   // interleaved [AF0,AS0,...|BF0,BS0,...]
__device__ __align__(16) float g_msg[NN * DD];
__device__ __align__(16) float g_pooled[NG * DD];
__device__ __align__(16) float g_y[NG * DD];
__device__ __align__(16) float g_t1[NG * 64];
__device__ __align__(16) float g_t2[NG * 32];
__device__ __align__(16) float g_t3[NG * 16];
__device__ __align__(16) float g_Wcat_n[128 * 512];  // interleaved cols
__device__ __align__(16) float g_Wcat_e[128 * 256];  // interleaved cols
__device__ __align__(16) float g_bcat_e[256];        // interleaved bias
__device__ __align__(16) float g_bn[512];

// ---------------- math helpers ----------------
__device__ __forceinline__ float fsp(float v) {        // softplus
    return (v > 20.0f) ? v : __logf(1.0f + __expf(v));
}
__device__ __forceinline__ float fsig(float v) {       // sigmoid
    return __fdividef(1.0f, 1.0f + __expf(-v));
}
__device__ __forceinline__ void mma_tf32(float c[4], const uint32_t a[4], const uint32_t b[2]) {
    asm volatile(
        "mma.sync.aligned.m16n8k8.row.col.f32.tf32.tf32.f32 "
        "{%0,%1,%2,%3}, {%4,%5,%6,%7}, {%8,%9}, {%0,%1,%2,%3};"
        : "+f"(c[0]), "+f"(c[1]), "+f"(c[2]), "+f"(c[3])
        : "r"(a[0]), "r"(a[1]), "r"(a[2]), "r"(a[3]), "r"(b[0]), "r"(b[1]));
}

// fragment compute over the current smem chunk (shared by all GEMM kernels)
#define MMA_CHUNK(Asrc, Bsrc)                                                          \
    do {                                                                               \
        _Pragma("unroll")                                                              \
        for (int ks = 0; ks < 4; ks++) {                                               \
            int k = ks << 3;                                                           \
            uint32_t a[2][4], b[8][2];                                                 \
            _Pragma("unroll")                                                          \
            for (int fm = 0; fm < 2; fm++) {                                           \
                int mb = warp_m * 32 + fm * 16 + mr;                                   \
                a[fm][0] = __float_as_uint((Asrc)[mb * AS_STRIDE + k + kc]);           \
                a[fm][1] = __float_as_uint((Asrc)[(mb + 8) * AS_STRIDE + k + kc]);     \
                a[fm][2] = __float_as_uint((Asrc)[mb * AS_STRIDE + k + kc + 4]);       \
                a[fm][3] = __float_as_uint((Asrc)[(mb + 8) * AS_STRIDE + k + kc + 4]); \
            }                                                                          \
            _Pragma("unroll")                                                          \
            for (int fn = 0; fn < 8; fn++) {                                           \
                int nb = warp_n * 64 + fn * 8 + mr;                                    \
                b[fn][0] = __float_as_uint((Bsrc)[(k + kc) * BS_STRIDE + nb]);         \
                b[fn][1] = __float_as_uint((Bsrc)[(k + kc + 4) * BS_STRIDE + nb]);     \
            }                                                                          \
            _Pragma("unroll")                                                          \
            for (int fm = 0; fm < 2; fm++)                                             \
                _Pragma("unroll")                                                      \
                for (int fn = 0; fn < 8; fn++) mma_tf32(c[fm][fn], a[fm], b[fn]);      \
        }                                                                              \
    } while (0)

// ---------------- generic tf32 GEMM: C = act(A[M,K] @ W[K,Ncols] + bias) ----------------
// grid: (Ncols/128, ceil(M/128)), 256 threads (8 warps: 4m x 2n).
__global__ __launch_bounds__(256) void mma_gemm(
    const float* __restrict__ A, const float* __restrict__ W,
    const float* __restrict__ bias, float* __restrict__ C,
    int M, int K, int Ncols, int act)
{
    __shared__ float As[128 * AS_STRIDE];
    __shared__ float Bs[32 * BS_STRIDE];
    const int tid = threadIdx.x;
    const int lane = tid & 31, wid = tid >> 5;
    const int warp_m = wid & 3, warp_n = wid >> 2;
    const int row0 = blockIdx.y * 128;
    const int col0 = blockIdx.x * 128;
    const int mr = lane >> 2, kc = lane & 3;

    float c[2][8][4];
#pragma unroll
    for (int i = 0; i < 2; i++)
#pragma unroll
        for (int j = 0; j < 8; j++)
#pragma unroll
            for (int q = 0; q < 4; q++) c[i][j][q] = 0.0f;

    const int nchunks = (K + 31) >> 5;
    const bool vec = (K & 31) == 0;

    if (vec) {
        // register-prefetch pipeline: LDG(ch+1) issued before MMA(ch)
        float4 pa[4], pb[4];
#pragma unroll
        for (int i = 0; i < 4; i++) {
            int lin = tid + i * 256;
            int r = lin >> 3, kv = (lin & 7) << 2;
            int gr = row0 + r;
            pa[i] = (gr < M) ? *(const float4*)(A + (size_t)gr * K + kv)
                             : make_float4(0.f, 0.f, 0.f, 0.f);
            int br = lin >> 5, nv = (lin & 31) << 2;
            pb[i] = *(const float4*)(W + (size_t)br * Ncols + col0 + nv);
        }
        for (int ch = 0; ch < nchunks; ch++) {
            if (ch) __syncthreads();   // previous chunk's MMA done reading smem
#pragma unroll
            for (int i = 0; i < 4; i++) {
                int lin = tid + i * 256;
                int r = lin >> 3, kv = (lin & 7) << 2;
                *(float4*)&As[r * AS_STRIDE + kv] = pa[i];
                int br = lin >> 5, nv = (lin & 31) << 2;
                *(float4*)&Bs[br * BS_STRIDE + nv] = pb[i];
            }
            __syncthreads();
            if (ch + 1 < nchunks) {
                int k0 = (ch + 1) << 5;
#pragma unroll
                for (int i = 0; i < 4; i++) {
                    int lin = tid + i * 256;
                    int r = lin >> 3, kv = (lin & 7) << 2;
                    int gr = row0 + r;
                    pa[i] = (gr < M) ? *(const float4*)(A + (size_t)gr * K + k0 + kv)
                                     : make_float4(0.f, 0.f, 0.f, 0.f);
                    int br = lin >> 5, nv = (lin & 31) << 2;
                    pb[i] = *(const float4*)(W + (size_t)(k0 + br) * Ncols + col0 + nv);
                }
            }
            MMA_CHUNK(As, Bs);
        }
    } else {
        for (int ch = 0; ch < nchunks; ch++) {
            int k0 = ch << 5;
            if (ch) __syncthreads();
#pragma unroll 4
            for (int lin = tid; lin < 128 * 32; lin += 256) {
                int r = lin >> 5, k = lin & 31;
                int gr = row0 + r, gk = k0 + k;
                As[r * AS_STRIDE + k] = (gr < M && gk < K) ? A[(size_t)gr * K + gk] : 0.0f;
            }
#pragma unroll 4
            for (int lin = tid; lin < 32 * 128; lin += 256) {
                int r = lin >> 7, n = lin & 127;
                int gk = k0 + r;
                Bs[r * BS_STRIDE + n] = (gk < K) ? W[(size_t)gk * Ncols + col0 + n] : 0.0f;
            }
            __syncthreads();
            MMA_CHUNK(As, Bs);
        }
    }

#pragma unroll
    for (int fm = 0; fm < 2; fm++) {
        int rr = row0 + warp_m * 32 + fm * 16 + mr;
#pragma unroll
        for (int fn = 0; fn < 8; fn++) {
            int cc = col0 + warp_n * 64 + fn * 8 + kc * 2;
            float b0 = 0.0f, b1 = 0.0f;
            if (bias) { b0 = bias[cc]; b1 = bias[cc + 1]; }
            float v0 = c[fm][fn][0] + b0, v1 = c[fm][fn][1] + b1;
            float v2 = c[fm][fn][2] + b0, v3 = c[fm][fn][3] + b1;
            if (act) {
                v0 = fmaxf(v0, 0.0f); v1 = fmaxf(v1, 0.0f);
                v2 = fmaxf(v2, 0.0f); v3 = fmaxf(v3, 0.0f);
            }
            if (rr < M) *(float2*)&C[(size_t)rr * Ncols + cc] = make_float2(v0, v1);
            if (rr + 8 < M) *(float2*)&C[(size_t)(rr + 8) * Ncols + cc] = make_float2(v2, v3);
        }
    }
}

// ---------------- fused edge GEMM + gating + scatter (register-prefetch pipelined) ----------------
__global__ __launch_bounds__(256) void edge_fused(const int* __restrict__ src,
                                                  const int* __restrict__ tgt)
{
    __shared__ float As[128 * AS_STRIDE];
    __shared__ float Bs[32 * BS_STRIDE];
    const int tid = threadIdx.x;
    const int lane = tid & 31, wid = tid >> 5;
    const int warp_m = wid & 3, warp_n = wid >> 2;
    const int row0 = blockIdx.y * 128;       // edge base (NE % 128 == 0)
    const int col0 = blockIdx.x * 128;       // 0 or 128 of 256 interleaved cols
    const int mr = lane >> 2, kc = lane & 3;

    float c[2][8][4];
#pragma unroll
    for (int i = 0; i < 2; i++)
#pragma unroll
        for (int j = 0; j < 8; j++)
#pragma unroll
            for (int q = 0; q < 4; q++) c[i][j][q] = 0.0f;

    float4 pa[4], pb[4];
#pragma unroll
    for (int i = 0; i < 4; i++) {
        int lin = tid + i * 256;
        int r = lin >> 3, kv = (lin & 7) << 2;
        pa[i] = *(const float4*)(g_e + (size_t)(row0 + r) * 128 + kv);
        int br = lin >> 5, nv = (lin & 31) << 2;
        pb[i] = *(const float4*)(g_Wcat_e + (size_t)br * 256 + col0 + nv);
    }
#pragma unroll 1
    for (int ch = 0; ch < 4; ch++) {
        if (ch) __syncthreads();
#pragma unroll
        for (int i = 0; i < 4; i++) {
            int lin = tid + i * 256;
            int r = lin >> 3, kv = (lin & 7) << 2;
            *(float4*)&As[r * AS_STRIDE + kv] = pa[i];
            int br = lin >> 5, nv = (lin & 31) << 2;
            *(float4*)&Bs[br * BS_STRIDE + nv] = pb[i];
        }
        __syncthreads();
        if (ch + 1 < 4) {
            int k0 = (ch + 1) << 5;
#pragma unroll
            for (int i = 0; i < 4; i++) {
                int lin = tid + i * 256;
                int r = lin >> 3, kv = (lin & 7) << 2;
                pa[i] = *(const float4*)(g_e + (size_t)(row0 + r) * 128 + k0 + kv);
                int br = lin >> 5, nv = (lin & 31) << 2;
                pb[i] = *(const float4*)(g_Wcat_e + (size_t)(k0 + br) * 256 + col0 + nv);
            }
        }
        MMA_CHUNK(As, Bs);
    }

    // ---- fused epilogue: gate + scatter ----
#pragma unroll
    for (int fm = 0; fm < 2; fm++) {
        int e1 = row0 + warp_m * 32 + fm * 16 + mr;
        int e2 = e1 + 8;
        int s1 = src[e1], t1 = tgt[e1];
        int s2 = src[e2], t2 = tgt[e2];
        const float2* sa1 = (const float2*)(g_ABn + (size_t)s1 * 512);
        const float2* ta1 = (const float2*)(g_ABn + (size_t)t1 * 512 + 256);
        const float2* sa2 = (const float2*)(g_ABn + (size_t)s2 * 512);
        const float2* ta2 = (const float2*)(g_ABn + (size_t)t2 * 512 + 256);
        float* m1 = g_msg + (size_t)s1 * DD;
        float* m2 = g_msg + (size_t)s2 * DD;
#pragma unroll
        for (int fn = 0; fn < 8; fn++) {
            int cc = col0 + warp_n * 64 + fn * 8 + kc * 2;
            int d = cc >> 1;
            float2 bi = *(const float2*)&g_bcat_e[cc];
            float2 u1 = sa1[d], v1 = ta1[d];
            float f1 = c[fm][fn][0] + bi.x + u1.x + v1.x;
            float w1 = c[fm][fn][1] + bi.y + u1.y + v1.y;
            atomicAdd(&m1[d], fsig(f1) * fsp(w1));
            float2 u2 = sa2[d], v2 = ta2[d];
            float f2 = c[fm][fn][2] + bi.x + u2.x + v2.x;
            float w2 = c[fm][fn][3] + bi.y + u2.y + v2.y;
            atomicAdd(&m2[d], fsig(f2) * fsp(w2));
        }
    }
}

// ---------------- small kernels ----------------
__global__ void zero_kernel(float* p, int n) {
    int i = blockIdx.x * blockDim.x + threadIdx.x;
    if (i < n) p[i] = 0.0f;
}

__global__ void pack_node(const float* __restrict__ Wf, const float* __restrict__ Ws) {
    int idx = blockIdx.x * blockDim.x + threadIdx.x;
    if (idx >= 128 * 512) return;
    int k = idx >> 9, c = idx & 511;
    float v;
    if (c < 256) {
        int d = c >> 1;
        v = (c & 1) ? Ws[k * 128 + d] : Wf[k * 128 + d];
    } else {
        int d = (c - 256) >> 1;
        v = (c & 1) ? Ws[(128 + k) * 128 + d] : Wf[(128 + k) * 128 + d];
    }
    g_Wcat_n[idx] = v;
}

__global__ void pack_edge(const float* __restrict__ Wf, const float* __restrict__ Ws,
                          const float* __restrict__ bf, const float* __restrict__ bs) {
    int idx = blockIdx.x * blockDim.x + threadIdx.x;
    if (idx >= 128 * 256) return;
    int k = idx >> 8, c = idx & 255;
    int d = c >> 1;
    g_Wcat_e[idx] = (c & 1) ? Ws[(256 + k) * 128 + d] : Wf[(256 + k) * 128 + d];
    if (idx < 256) g_bcat_e[idx] = (idx & 1) ? bs[idx >> 1] : bf[idx >> 1];
}

__global__ void bn_stats() {
    int d = threadIdx.x;
    float s = 0.0f, ss = 0.0f;
    for (int r = blockIdx.x; r < NN; r += gridDim.x) {
        float v = g_msg[(size_t)r * DD + d];
        s += v; ss += v * v;
    }
    atomicAdd(&g_bn[d], s);
    atomicAdd(&g_bn[128 + d], ss);
}

__global__ void bn_finalize(const float* __restrict__ gamma, const float* __restrict__ beta) {
    int d = threadIdx.x;
    float mu  = g_bn[d] * (1.0f / NN);
    float var = g_bn[128 + d] * (1.0f / NN) - mu * mu;
    float rstd = rsqrtf(var + 1e-5f);
    float sc = rstd * gamma[d];
    g_bn[256 + d] = sc;
    g_bn[384 + d] = beta[d] - mu * sc;
}

__global__ __launch_bounds__(128) void node_update(const int* __restrict__ batch, int cur) {
    int d = threadIdx.x;
    int r0 = blockIdx.x * 32;
    int rend = min(r0 + 32, NN);
    const float* xin = g_x[cur];
    float* xout = g_x[cur ^ 1];
    float sc = g_bn[256 + d], sh = g_bn[384 + d];
    float acc = 0.0f;
    int curb = batch[r0];
    for (int r = r0; r < rend; r++) {
        int b = batch[r];
        if (b != curb) {
            atomicAdd(&g_pooled[(size_t)curb * DD + d], acc);
            acc = 0.0f; curb = b;
        }
        size_t idx = (size_t)r * DD + d;
        float v = fsp(xin[idx] + g_msg[idx] * sc + sh);
        xout[idx] = v;
        acc += v;
    }
    atomicAdd(&g_pooled[(size_t)curb * DD + d], acc);
}

__global__ void small_gemm(const float* __restrict__ A, const float* __restrict__ W,
                           const float* __restrict__ b, float* __restrict__ C,
                           int M, int K, int Nc, int accum, int act) {
    int idx = blockIdx.x * blockDim.x + threadIdx.x;
    if (idx >= M * Nc) return;
    int r = idx / Nc, c = idx % Nc;
    float s = b[c];
    for (int k = 0; k < K; k++) s = fmaf(A[r * K + k], W[k * Nc + c], s);
    if (accum) s += C[idx];
    if (act) s = fmaxf(s, 0.0f);
    C[idx] = s;
}

// ---------------- host ----------------
static float* symaddr(const void* sym) {
    void* p = nullptr;
    cudaGetSymbolAddress(&p, sym);
    return (float*)p;
}

extern "C" void kernel_launch(void* const* d_in, const int* in_sizes, int n_in,
                              void* d_out, int out_size)
{
    const float* x_in = (const float*)d_in[0];
    const float* ea   = (const float*)d_in[1];
    const int*   esrc = (const int*)d_in[2];
    const int*   etgt = (const int*)d_in[3];
    const int*   nbat = (const int*)d_in[4];
    const float* Wn   = (const float*)d_in[5];
    const float* bne  = (const float*)d_in[6];
    const float* We   = (const float*)d_in[7];
    const float* bee  = (const float*)d_in[8];
    const float* Wf   = (const float*)d_in[9];
    const float* bf   = (const float*)d_in[10];
    const float* Ws   = (const float*)d_in[11];
    const float* bs   = (const float*)d_in[12];
    int iWg = 15, ibg = 16, iga = 13, ibe = 14;
    if (in_sizes[13] == 5 * 128 * 128) { iWg = 13; ibg = 14; iga = 15; ibe = 16; }
    const float* Wg    = (const float*)d_in[iWg];
    const float* bg    = (const float*)d_in[ibg];
    const float* gamma = (const float*)d_in[iga];
    const float* beta  = (const float*)d_in[ibe];
    const float* Wr1 = (const float*)d_in[17]; const float* br1 = (const float*)d_in[18];
    const float* Wr2 = (const float*)d_in[19]; const float* br2 = (const float*)d_in[20];
    const float* Wr3 = (const float*)d_in[21]; const float* br3 = (const float*)d_in[22];
    const float* Wr4 = (const float*)d_in[23]; const float* br4 = (const float*)d_in[24];
    float* out = (float*)d_out;

    float* xbuf   = symaddr(g_x);
    float* ebuf   = symaddr(g_e);
    float* abn    = symaddr(g_ABn);
    float* msg    = symaddr(g_msg);
    float* pooled = symaddr(g_pooled);
    float* ybuf   = symaddr(g_y);
    float* t1     = symaddr(g_t1);
    float* t2     = symaddr(g_t2);
    float* t3     = symaddr(g_t3);
    float* wcn    = symaddr(g_Wcat_n);
    float* bnb    = symaddr(g_bn);

    // embeddings (tensor-core, scalar-load path for odd K)
    mma_gemm<<<dim3(1, (NN + 127) / 128), 256>>>(x_in, Wn, bne, xbuf, NN, 92, 128, 1);
    mma_gemm<<<dim3(1, (NE + 127) / 128), 256>>>(ea, We, bee, ebuf, NE, 41, 128, 1);
    zero_kernel<<<(NG * DD + 255) / 256, 256>>>(ybuf, NG * DD);

    int cur = 0;
    for (int i = 0; i < 5; i++) {
        const float* Wfi = Wf + (size_t)i * 384 * 128;
        const float* Wsi = Ws + (size_t)i * 384 * 128;
        pack_node<<<(128 * 512 + 255) / 256, 256>>>(Wfi, Wsi);
        pack_edge<<<(128 * 256 + 255) / 256, 256>>>(Wfi, Wsi, bf + i * 128, bs + i * 128);

        mma_gemm<<<dim3(4, (NN + 127) / 128), 256>>>(
            xbuf + (size_t)cur * NN * DD, wcn, nullptr, abn, NN, 128, 512, 0);

        zero_kernel<<<(NN * DD + 255) / 256, 256>>>(msg, NN * DD);
        edge_fused<<<dim3(2, NE / 128), 256>>>(esrc, etgt);

        zero_kernel<<<1, 256>>>(bnb, 256);
        bn_stats<<<512, 128>>>();
        bn_finalize<<<1, 128>>>(gamma + i * 128, beta + i * 128);

        zero_kernel<<<(NG * DD + 255) / 256, 256>>>(pooled, NG * DD);
        node_update<<<(NN + 31) / 32, 128>>>(nbat, cur);

        small_gemm<<<(NG * 128 + 255) / 256, 256>>>(pooled, Wg + (size_t)i * 128 * 128,
                                                    bg + i * 128, ybuf, NG, 128, 128, 1, 0);
        cur ^= 1;
    }

    small_gemm<<<(NG * 64 + 255) / 256, 256>>>(ybuf, Wr1, br1, t1, NG, 128, 64, 0, 1);
    small_gemm<<<(NG * 32 + 255) / 256, 256>>>(t1, Wr2, br2, t2, NG, 64, 32, 0, 1);
    small_gemm<<<(NG * 16 + 255) / 256, 256>>>(t2, Wr3, br3, t3, NG, 32, 16, 0, 1);
    small_gemm<<<(NG * 1 + 255) / 256, 256>>>(t3, Wr4, br4, out, NG, 16, 1, 0, 1);
}

// round 9
// speedup vs baseline: 3.1443x; 1.1097x over previous
#include <cuda_runtime.h>
#include <cuda_bf16.h>
#include <math.h>
#include <stdint.h>

#define NN 50000
#define NE 400000
#define DD 128
#define NG 512

#define AS_STRIDE 36
#define BS_STRIDE 136
#define BSTR 40           // bf16 smem stride (conflict-free: 20*mr+tc distinct mod 32)

// ---------------- device scratch ----------------
__device__ __align__(16) float g_x[2][NN * DD];
__device__ __align__(16) __nv_bfloat16 g_e[NE * DD];        // edge embeddings (bf16)
__device__ __align__(16) __nv_bfloat16 g_eap[NE * 64];      // padded edge attrs (bf16)
__device__ __align__(16) __nv_bfloat16 g_Wep[128 * 64];     // We packed n-major [n][k]
__device__ __align__(16) __nv_bfloat16 g_Wce[256 * 128];    // edge W packed n-major, interleaved f/s
__device__ __align__(16) float g_ABn[NN * 512];             // interleaved [AF0,AS0,...|BF0,BS0,...]
__device__ __align__(16) float g_msg[NN * DD];
__device__ __align__(16) float g_pooled[NG * DD];
__device__ __align__(16) float g_y[NG * DD];
__device__ __align__(16) float g_t1[NG * 64];
__device__ __align__(16) float g_t2[NG * 32];
__device__ __align__(16) float g_t3[NG * 16];
__device__ __align__(16) float g_Wcat_n[128 * 512];         // tf32 node W (k-major, interleaved cols)
__device__ __align__(16) float g_bcat_e[256];               // interleaved edge bias (f32)
__device__ __align__(16) float g_bn[512];

// ---------------- math helpers ----------------
__device__ __forceinline__ float fsp(float v) {
    return (v > 20.0f) ? v : __logf(1.0f + __expf(v));
}
__device__ __forceinline__ float fsig(float v) {
    return __fdividef(1.0f, 1.0f + __expf(-v));
}
__device__ __forceinline__ void mma_tf32(float c[4], const uint32_t a[4], const uint32_t b[2]) {
    asm volatile(
        "mma.sync.aligned.m16n8k8.row.col.f32.tf32.tf32.f32 "
        "{%0,%1,%2,%3}, {%4,%5,%6,%7}, {%8,%9}, {%0,%1,%2,%3};"
        : "+f"(c[0]), "+f"(c[1]), "+f"(c[2]), "+f"(c[3])
        : "r"(a[0]), "r"(a[1]), "r"(a[2]), "r"(a[3]), "r"(b[0]), "r"(b[1]));
}
__device__ __forceinline__ void mma_bf16(float c[4], const uint32_t a[4], const uint32_t b[2]) {
    asm volatile(
        "mma.sync.aligned.m16n8k16.row.col.f32.bf16.bf16.f32 "
        "{%0,%1,%2,%3}, {%4,%5,%6,%7}, {%8,%9}, {%0,%1,%2,%3};"
        : "+f"(c[0]), "+f"(c[1]), "+f"(c[2]), "+f"(c[3])
        : "r"(a[0]), "r"(a[1]), "r"(a[2]), "r"(a[3]), "r"(b[0]), "r"(b[1]));
}

// tf32 fragment compute over current smem chunk
#define MMA_CHUNK(Asrc, Bsrc)                                                          \
    do {                                                                               \
        _Pragma("unroll")                                                              \
        for (int ks = 0; ks < 4; ks++) {                                               \
            int k = ks << 3;                                                           \
            uint32_t a[2][4], b[8][2];                                                 \
            _Pragma("unroll")                                                          \
            for (int fm = 0; fm < 2; fm++) {                                           \
                int mb = warp_m * 32 + fm * 16 + mr;                                   \
                a[fm][0] = __float_as_uint((Asrc)[mb * AS_STRIDE + k + kc]);           \
                a[fm][1] = __float_as_uint((Asrc)[(mb + 8) * AS_STRIDE + k + kc]);     \
                a[fm][2] = __float_as_uint((Asrc)[mb * AS_STRIDE + k + kc + 4]);       \
                a[fm][3] = __float_as_uint((Asrc)[(mb + 8) * AS_STRIDE + k + kc + 4]); \
            }                                                                          \
            _Pragma("unroll")                                                          \
            for (int fn = 0; fn < 8; fn++) {                                           \
                int nb = warp_n * 64 + fn * 8 + mr;                                    \
                b[fn][0] = __float_as_uint((Bsrc)[(k + kc) * BS_STRIDE + nb]);         \
                b[fn][1] = __float_as_uint((Bsrc)[(k + kc + 4) * BS_STRIDE + nb]);     \
            }                                                                          \
            _Pragma("unroll")                                                          \
            for (int fm = 0; fm < 2; fm++)                                             \
                _Pragma("unroll")                                                      \
                for (int fn = 0; fn < 8; fn++) mma_tf32(c[fm][fn], a[fm], b[fn]);      \
        }                                                                              \
    } while (0)

// bf16 fragment compute over current 32-k smem chunk (As/Bs: bf16, stride BSTR)
#define BMMA_CHUNK(Asrc, Bsrc)                                                         \
    do {                                                                               \
        _Pragma("unroll")                                                              \
        for (int ks = 0; ks < 2; ks++) {                                               \
            int kk = (ks << 4) + (kc << 1);                                            \
            uint32_t a[2][4], b[8][2];                                                 \
            _Pragma("unroll")                                                          \
            for (int fm = 0; fm < 2; fm++) {                                           \
                int mb = warp_m * 32 + fm * 16 + mr;                                   \
                a[fm][0] = *(const uint32_t*)&(Asrc)[mb * BSTR + kk];                  \
                a[fm][1] = *(const uint32_t*)&(Asrc)[(mb + 8) * BSTR + kk];            \
                a[fm][2] = *(const uint32_t*)&(Asrc)[mb * BSTR + kk + 8];              \
                a[fm][3] = *(const uint32_t*)&(Asrc)[(mb + 8) * BSTR + kk + 8];        \
            }                                                                          \
            _Pragma("unroll")                                                          \
            for (int fn = 0; fn < 8; fn++) {                                           \
                int nb = warp_n * 64 + fn * 8 + mr;                                    \
                b[fn][0] = *(const uint32_t*)&(Bsrc)[nb * BSTR + kk];                  \
                b[fn][1] = *(const uint32_t*)&(Bsrc)[nb * BSTR + kk + 8];              \
            }                                                                          \
            _Pragma("unroll")                                                          \
            for (int fm = 0; fm < 2; fm++)                                             \
                _Pragma("unroll")                                                      \
                for (int fn = 0; fn < 8; fn++) mma_bf16(c[fm][fn], a[fm], b[fn]);      \
        }                                                                              \
    } while (0)

// ---------------- tf32 GEMM (node path + x embedding) ----------------
__global__ __launch_bounds__(256) void mma_gemm(
    const float* __restrict__ A, const float* __restrict__ W,
    const float* __restrict__ bias, float* __restrict__ C,
    int M, int K, int Ncols, int act)
{
    __shared__ float As[128 * AS_STRIDE];
    __shared__ float Bs[32 * BS_STRIDE];
    const int tid = threadIdx.x;
    const int lane = tid & 31, wid = tid >> 5;
    const int warp_m = wid & 3, warp_n = wid >> 2;
    const int row0 = blockIdx.y * 128;
    const int col0 = blockIdx.x * 128;
    const int mr = lane >> 2, kc = lane & 3;

    float c[2][8][4];
#pragma unroll
    for (int i = 0; i < 2; i++)
#pragma unroll
        for (int j = 0; j < 8; j++)
#pragma unroll
            for (int q = 0; q < 4; q++) c[i][j][q] = 0.0f;

    const int nchunks = (K + 31) >> 5;
    const bool vec = (K & 31) == 0;

    if (vec) {
        float4 pa[4], pb[4];
#pragma unroll
        for (int i = 0; i < 4; i++) {
            int lin = tid + i * 256;
            int r = lin >> 3, kv = (lin & 7) << 2;
            int gr = row0 + r;
            pa[i] = (gr < M) ? *(const float4*)(A + (size_t)gr * K + kv)
                             : make_float4(0.f, 0.f, 0.f, 0.f);
            int br = lin >> 5, nv = (lin & 31) << 2;
            pb[i] = *(const float4*)(W + (size_t)br * Ncols + col0 + nv);
        }
        for (int ch = 0; ch < nchunks; ch++) {
            if (ch) __syncthreads();
#pragma unroll
            for (int i = 0; i < 4; i++) {
                int lin = tid + i * 256;
                int r = lin >> 3, kv = (lin & 7) << 2;
                *(float4*)&As[r * AS_STRIDE + kv] = pa[i];
                int br = lin >> 5, nv = (lin & 31) << 2;
                *(float4*)&Bs[br * BS_STRIDE + nv] = pb[i];
            }
            __syncthreads();
            if (ch + 1 < nchunks) {
                int k0 = (ch + 1) << 5;
#pragma unroll
                for (int i = 0; i < 4; i++) {
                    int lin = tid + i * 256;
                    int r = lin >> 3, kv = (lin & 7) << 2;
                    int gr = row0 + r;
                    pa[i] = (gr < M) ? *(const float4*)(A + (size_t)gr * K + k0 + kv)
                                     : make_float4(0.f, 0.f, 0.f, 0.f);
                    int br = lin >> 5, nv = (lin & 31) << 2;
                    pb[i] = *(const float4*)(W + (size_t)(k0 + br) * Ncols + col0 + nv);
                }
            }
            MMA_CHUNK(As, Bs);
        }
    } else {
        for (int ch = 0; ch < nchunks; ch++) {
            int k0 = ch << 5;
            if (ch) __syncthreads();
#pragma unroll 4
            for (int lin = tid; lin < 128 * 32; lin += 256) {
                int r = lin >> 5, k = lin & 31;
                int gr = row0 + r, gk = k0 + k;
                As[r * AS_STRIDE + k] = (gr < M && gk < K) ? A[(size_t)gr * K + gk] : 0.0f;
            }
#pragma unroll 4
            for (int lin = tid; lin < 32 * 128; lin += 256) {
                int r = lin >> 7, n = lin & 127;
                int gk = k0 + r;
                Bs[r * BS_STRIDE + n] = (gk < K) ? W[(size_t)gk * Ncols + col0 + n] : 0.0f;
            }
            __syncthreads();
            MMA_CHUNK(As, Bs);
        }
    }

#pragma unroll
    for (int fm = 0; fm < 2; fm++) {
        int rr = row0 + warp_m * 32 + fm * 16 + mr;
#pragma unroll
        for (int fn = 0; fn < 8; fn++) {
            int cc = col0 + warp_n * 64 + fn * 8 + kc * 2;
            float b0 = 0.0f, b1 = 0.0f;
            if (bias) { b0 = bias[cc]; b1 = bias[cc + 1]; }
            float v0 = c[fm][fn][0] + b0, v1 = c[fm][fn][1] + b1;
            float v2 = c[fm][fn][2] + b0, v3 = c[fm][fn][3] + b1;
            if (act) {
                v0 = fmaxf(v0, 0.0f); v1 = fmaxf(v1, 0.0f);
                v2 = fmaxf(v2, 0.0f); v3 = fmaxf(v3, 0.0f);
            }
            if (rr < M) *(float2*)&C[(size_t)rr * Ncols + cc] = make_float2(v0, v1);
            if (rr + 8 < M) *(float2*)&C[(size_t)(rr + 8) * Ncols + cc] = make_float2(v2, v3);
        }
    }
}

// ---------------- bf16 GEMM (edge embedding): C_bf16 = relu(A_bf16 @ Wn^T + bias) ----------------
// A: [M,K] bf16 row-major; Wn: [Ntot,K] bf16 n-major; grid (Ncols/128, M/128). K % 32 == 0.
__global__ __launch_bounds__(256) void bf16_gemm(
    const __nv_bfloat16* __restrict__ A, const __nv_bfloat16* __restrict__ Wn,
    const float* __restrict__ bias, __nv_bfloat16* __restrict__ C,
    int M, int K, int Ncols, int act)
{
    __shared__ __align__(16) __nv_bfloat16 As[2][128 * BSTR];
    __shared__ __align__(16) __nv_bfloat16 Bs[2][128 * BSTR];
    const int tid = threadIdx.x;
    const int lane = tid & 31, wid = tid >> 5;
    const int warp_m = wid & 3, warp_n = wid >> 2;
    const int row0 = blockIdx.y * 128;
    const int col0 = blockIdx.x * 128;
    const int mr = lane >> 2, kc = lane & 3;
    const int lr = tid >> 2, lq = (tid & 3) << 3;   // load map: r, k-offset(8 bf16)
    const int nch = K >> 5;

    float c[2][8][4];
#pragma unroll
    for (int i = 0; i < 2; i++)
#pragma unroll
        for (int j = 0; j < 8; j++)
#pragma unroll
            for (int q = 0; q < 4; q++) c[i][j][q] = 0.0f;

    uint4 pa[2], pb[2];
#pragma unroll
    for (int i = 0; i < 2; i++) {
        int r = lr + i * 64;
        int gr = row0 + r;
        pa[i] = (gr < M) ? *(const uint4*)(A + (size_t)gr * K + lq)
                         : make_uint4(0u, 0u, 0u, 0u);
        pb[i] = *(const uint4*)(Wn + (size_t)(col0 + r) * K + lq);
    }
#pragma unroll
    for (int i = 0; i < 2; i++) {
        int r = lr + i * 64;
        *(uint4*)&As[0][r * BSTR + lq] = pa[i];
        *(uint4*)&Bs[0][r * BSTR + lq] = pb[i];
    }
    for (int ch = 0; ch < nch; ch++) {
        int buf = ch & 1;
        if (ch + 1 < nch) {
            int k0 = (ch + 1) << 5;
#pragma unroll
            for (int i = 0; i < 2; i++) {
                int r = lr + i * 64;
                int gr = row0 + r;
                pa[i] = (gr < M) ? *(const uint4*)(A + (size_t)gr * K + k0 + lq)
                                 : make_uint4(0u, 0u, 0u, 0u);
                pb[i] = *(const uint4*)(Wn + (size_t)(col0 + r) * K + k0 + lq);
            }
        }
        __syncthreads();
        BMMA_CHUNK(As[buf], Bs[buf]);
        if (ch + 1 < nch) {
#pragma unroll
            for (int i = 0; i < 2; i++) {
                int r = lr + i * 64;
                *(uint4*)&As[buf ^ 1][r * BSTR + lq] = pa[i];
                *(uint4*)&Bs[buf ^ 1][r * BSTR + lq] = pb[i];
            }
        }
    }

#pragma unroll
    for (int fm = 0; fm < 2; fm++) {
        int rr = row0 + warp_m * 32 + fm * 16 + mr;
#pragma unroll
        for (int fn = 0; fn < 8; fn++) {
            int cc = col0 + warp_n * 64 + fn * 8 + kc * 2;
            float b0 = bias[cc], b1 = bias[cc + 1];
            float v0 = c[fm][fn][0] + b0, v1 = c[fm][fn][1] + b1;
            float v2 = c[fm][fn][2] + b0, v3 = c[fm][fn][3] + b1;
            if (act) {
                v0 = fmaxf(v0, 0.0f); v1 = fmaxf(v1, 0.0f);
                v2 = fmaxf(v2, 0.0f); v3 = fmaxf(v3, 0.0f);
            }
            if (rr < M) {
                __nv_bfloat162 p = __floats2bfloat162_rn(v0, v1);
                *(__nv_bfloat162*)&C[(size_t)rr * Ncols + cc] = p;
            }
            if (rr + 8 < M) {
                __nv_bfloat162 p = __floats2bfloat162_rn(v2, v3);
                *(__nv_bfloat162*)&C[(size_t)(rr + 8) * Ncols + cc] = p;
            }
        }
    }
}

// ---------------- fused bf16 edge GEMM + gating + scatter ----------------
// A = g_e [NE,128] bf16, W = g_Wce [256,128] bf16 n-major. grid (2, NE/128).
__global__ __launch_bounds__(256) void edge_fused(const int* __restrict__ src,
                                                  const int* __restrict__ tgt)
{
    __shared__ __align__(16) __nv_bfloat16 As[2][128 * BSTR];
    __shared__ __align__(16) __nv_bfloat16 Bs[2][128 * BSTR];
    const int tid = threadIdx.x;
    const int lane = tid & 31, wid = tid >> 5;
    const int warp_m = wid & 3, warp_n = wid >> 2;
    const int row0 = blockIdx.y * 128;
    const int col0 = blockIdx.x * 128;
    const int mr = lane >> 2, kc = lane & 3;
    const int lr = tid >> 2, lq = (tid & 3) << 3;

    // early index loads (latency hidden under mainloop)
    int ebase = row0 + warp_m * 32 + mr;
    int s0 = src[ebase], t0 = tgt[ebase];
    int s1 = src[ebase + 8], t1 = tgt[ebase + 8];
    int s2 = src[ebase + 16], t2 = tgt[ebase + 16];
    int s3 = src[ebase + 24], t3 = tgt[ebase + 24];

    float c[2][8][4];
#pragma unroll
    for (int i = 0; i < 2; i++)
#pragma unroll
        for (int j = 0; j < 8; j++)
#pragma unroll
            for (int q = 0; q < 4; q++) c[i][j][q] = 0.0f;

    uint4 pa[2], pb[2];
#pragma unroll
    for (int i = 0; i < 2; i++) {
        int r = lr + i * 64;
        pa[i] = *(const uint4*)(g_e + (size_t)(row0 + r) * 128 + lq);
        pb[i] = *(const uint4*)(g_Wce + (size_t)(col0 + r) * 128 + lq);
    }
#pragma unroll
    for (int i = 0; i < 2; i++) {
        int r = lr + i * 64;
        *(uint4*)&As[0][r * BSTR + lq] = pa[i];
        *(uint4*)&Bs[0][r * BSTR + lq] = pb[i];
    }
#pragma unroll 1
    for (int ch = 0; ch < 4; ch++) {
        int buf = ch & 1;
        if (ch + 1 < 4) {
            int k0 = (ch + 1) << 5;
#pragma unroll
            for (int i = 0; i < 2; i++) {
                int r = lr + i * 64;
                pa[i] = *(const uint4*)(g_e + (size_t)(row0 + r) * 128 + k0 + lq);
                pb[i] = *(const uint4*)(g_Wce + (size_t)(col0 + r) * 128 + k0 + lq);
            }
        }
        __syncthreads();
        BMMA_CHUNK(As[buf], Bs[buf]);
        if (ch + 1 < 4) {
#pragma unroll
            for (int i = 0; i < 2; i++) {
                int r = lr + i * 64;
                *(uint4*)&As[buf ^ 1][r * BSTR + lq] = pa[i];
                *(uint4*)&Bs[buf ^ 1][r * BSTR + lq] = pb[i];
            }
        }
    }

    // ---- fused epilogue: gate + scatter ----
    int ss[4] = {s0, s1, s2, s3};
    int tt[4] = {t0, t1, t2, t3};
#pragma unroll
    for (int fm = 0; fm < 2; fm++) {
        int i1 = fm * 2, i2 = fm * 2 + 1;
        const float2* sa1 = (const float2*)(g_ABn + (size_t)ss[i1] * 512);
        const float2* ta1 = (const float2*)(g_ABn + (size_t)tt[i1] * 512 + 256);
        const float2* sa2 = (const float2*)(g_ABn + (size_t)ss[i2] * 512);
        const float2* ta2 = (const float2*)(g_ABn + (size_t)tt[i2] * 512 + 256);
        float* m1 = g_msg + (size_t)ss[i1] * DD;
        float* m2 = g_msg + (size_t)ss[i2] * DD;
#pragma unroll
        for (int fn = 0; fn < 8; fn++) {
            int cc = col0 + warp_n * 64 + fn * 8 + kc * 2;
            int d = cc >> 1;
            float2 bi = *(const float2*)&g_bcat_e[cc];
            float2 u1 = sa1[d], v1 = ta1[d];
            float f1 = c[fm][fn][0] + bi.x + u1.x + v1.x;
            float w1 = c[fm][fn][1] + bi.y + u1.y + v1.y;
            atomicAdd(&m1[d], fsig(f1) * fsp(w1));
            float2 u2 = sa2[d], v2 = ta2[d];
            float f2 = c[fm][fn][2] + bi.x + u2.x + v2.x;
            float w2 = c[fm][fn][3] + bi.y + u2.y + v2.y;
            atomicAdd(&m2[d], fsig(f2) * fsp(w2));
        }
    }
}

// ---------------- small kernels ----------------
__global__ void zero_kernel(float* p, int n) {
    int i = blockIdx.x * blockDim.x + threadIdx.x;
    if (i < n) p[i] = 0.0f;
}

__global__ void pad_ea(const float* __restrict__ ea) {
    int idx = blockIdx.x * blockDim.x + threadIdx.x;
    if (idx >= NE * 64) return;
    int e = idx >> 6, k = idx & 63;
    g_eap[idx] = __float2bfloat16(k < 41 ? ea[e * 41 + k] : 0.0f);
}

__global__ void pack_We(const float* __restrict__ We) {
    int idx = blockIdx.x * blockDim.x + threadIdx.x;
    if (idx >= 128 * 64) return;
    int n = idx >> 6, k = idx & 63;
    g_Wep[idx] = __float2bfloat16(k < 41 ? We[k * 128 + n] : 0.0f);
}

__global__ void pack_node(const float* __restrict__ Wf, const float* __restrict__ Ws) {
    int idx = blockIdx.x * blockDim.x + threadIdx.x;
    if (idx >= 128 * 512) return;
    int k = idx >> 9, c = idx & 511;
    float v;
    if (c < 256) {
        int d = c >> 1;
        v = (c & 1) ? Ws[k * 128 + d] : Wf[k * 128 + d];
    } else {
        int d = (c - 256) >> 1;
        v = (c & 1) ? Ws[(128 + k) * 128 + d] : Wf[(128 + k) * 128 + d];
    }
    g_Wcat_n[idx] = v;
}

// edge weights -> bf16 n-major [256 n][128 k], interleaved f/s on n
__global__ void pack_edge(const float* __restrict__ Wf, const float* __restrict__ Ws,
                          const float* __restrict__ bf, const float* __restrict__ bs) {
    int idx = blockIdx.x * blockDim.x + threadIdx.x;
    if (idx >= 256 * 128) return;
    int n = idx >> 7, k = idx & 127;
    int d = n >> 1;
    float v = (n & 1) ? Ws[(256 + k) * 128 + d] : Wf[(256 + k) * 128 + d];
    g_Wce[idx] = __float2bfloat16(v);
    if (idx < 256) g_bcat_e[idx] = (idx & 1) ? bs[idx >> 1] : bf[idx >> 1];
}

__global__ void bn_stats() {
    int d = threadIdx.x;
    float s = 0.0f, ss = 0.0f;
    for (int r = blockIdx.x; r < NN; r += gridDim.x) {
        float v = g_msg[(size_t)r * DD + d];
        s += v; ss += v * v;
    }
    atomicAdd(&g_bn[d], s);
    atomicAdd(&g_bn[128 + d], ss);
}

__global__ void bn_finalize(const float* __restrict__ gamma, const float* __restrict__ beta) {
    int d = threadIdx.x;
    float mu  = g_bn[d] * (1.0f / NN);
    float var = g_bn[128 + d] * (1.0f / NN) - mu * mu;
    float rstd = rsqrtf(var + 1e-5f);
    float sc = rstd * gamma[d];
    g_bn[256 + d] = sc;
    g_bn[384 + d] = beta[d] - mu * sc;
}

__global__ __launch_bounds__(128) void node_update(const int* __restrict__ batch, int cur) {
    int d = threadIdx.x;
    int r0 = blockIdx.x * 32;
    int rend = min(r0 + 32, NN);
    const float* xin = g_x[cur];
    float* xout = g_x[cur ^ 1];
    float sc = g_bn[256 + d], sh = g_bn[384 + d];
    float acc = 0.0f;
    int curb = batch[r0];
    for (int r = r0; r < rend; r++) {
        int b = batch[r];
        if (b != curb) {
            atomicAdd(&g_pooled[(size_t)curb * DD + d], acc);
            acc = 0.0f; curb = b;
        }
        size_t idx = (size_t)r * DD + d;
        float v = fsp(xin[idx] + g_msg[idx] * sc + sh);
        xout[idx] = v;
        acc += v;
    }
    atomicAdd(&g_pooled[(size_t)curb * DD + d], acc);
}

__global__ void small_gemm(const float* __restrict__ A, const float* __restrict__ W,
                           const float* __restrict__ b, float* __restrict__ C,
                           int M, int K, int Nc, int accum, int act) {
    int idx = blockIdx.x * blockDim.x + threadIdx.x;
    if (idx >= M * Nc) return;
    int r = idx / Nc, c = idx % Nc;
    float s = b[c];
    for (int k = 0; k < K; k++) s = fmaf(A[r * K + k], W[k * Nc + c], s);
    if (accum) s += C[idx];
    if (act) s = fmaxf(s, 0.0f);
    C[idx] = s;
}

// ---------------- host ----------------
static float* symaddr(const void* sym) {
    void* p = nullptr;
    cudaGetSymbolAddress(&p, sym);
    return (float*)p;
}

extern "C" void kernel_launch(void* const* d_in, const int* in_sizes, int n_in,
                              void* d_out, int out_size)
{
    const float* x_in = (const float*)d_in[0];
    const float* ea   = (const float*)d_in[1];
    const int*   esrc = (const int*)d_in[2];
    const int*   etgt = (const int*)d_in[3];
    const int*   nbat = (const int*)d_in[4];
    const float* Wn   = (const float*)d_in[5];
    const float* bne  = (const float*)d_in[6];
    const float* We   = (const float*)d_in[7];
    const float* bee  = (const float*)d_in[8];
    const float* Wf   = (const float*)d_in[9];
    const float* bf   = (const float*)d_in[10];
    const float* Ws   = (const float*)d_in[11];
    const float* bs   = (const float*)d_in[12];
    int iWg = 15, ibg = 16, iga = 13, ibe = 14;
    if (in_sizes[13] == 5 * 128 * 128) { iWg = 13; ibg = 14; iga = 15; ibe = 16; }
    const float* Wg    = (const float*)d_in[iWg];
    const float* bg    = (const float*)d_in[ibg];
    const float* gamma = (const float*)d_in[iga];
    const float* beta  = (const float*)d_in[ibe];
    const float* Wr1 = (const float*)d_in[17]; const float* br1 = (const float*)d_in[18];
    const float* Wr2 = (const float*)d_in[19]; const float* br2 = (const float*)d_in[20];
    const float* Wr3 = (const float*)d_in[21]; const float* br3 = (const float*)d_in[22];
    const float* Wr4 = (const float*)d_in[23]; const float* br4 = (const float*)d_in[24];
    float* out = (float*)d_out;

    float* xbuf   = symaddr(g_x);
    float* abn    = symaddr(g_ABn);
    float* msg    = symaddr(g_msg);
    float* pooled = symaddr(g_pooled);
    float* ybuf   = symaddr(g_y);
    float* t1     = symaddr(g_t1);
    float* t2     = symaddr(g_t2);
    float* t3     = symaddr(g_t3);
    float* wcn    = symaddr(g_Wcat_n);
    float* bnb    = symaddr(g_bn);
    __nv_bfloat16* ebuf = (__nv_bfloat16*)symaddr(g_e);
    __nv_bfloat16* eap  = (__nv_bfloat16*)symaddr(g_eap);
    __nv_bfloat16* wep  = (__nv_bfloat16*)symaddr(g_Wep);

    // embeddings: x tf32 (scalar K=92 path); edge via padded bf16 pipeline
    mma_gemm<<<dim3(1, (NN + 127) / 128), 256>>>(x_in, Wn, bne, xbuf, NN, 92, 128, 1);
    pad_ea<<<(NE * 64) / 256, 256>>>(ea);
    pack_We<<<(128 * 64 + 255) / 256, 256>>>(We);
    bf16_gemm<<<dim3(1, NE / 128), 256>>>(eap, wep, bee, ebuf, NE, 64, 128, 1);
    zero_kernel<<<(NG * DD + 255) / 256, 256>>>(ybuf, NG * DD);

    int cur = 0;
    for (int i = 0; i < 5; i++) {
        const float* Wfi = Wf + (size_t)i * 384 * 128;
        const float* Wsi = Ws + (size_t)i * 384 * 128;
        pack_node<<<(128 * 512 + 255) / 256, 256>>>(Wfi, Wsi);
        pack_edge<<<(256 * 128 + 255) / 256, 256>>>(Wfi, Wsi, bf + i * 128, bs + i * 128);

        mma_gemm<<<dim3(4, (NN + 127) / 128), 256>>>(
            xbuf + (size_t)cur * NN * DD, wcn, nullptr, abn, NN, 128, 512, 0);

        zero_kernel<<<(NN * DD + 255) / 256, 256>>>(msg, NN * DD);
        edge_fused<<<dim3(2, NE / 128), 256>>>(esrc, etgt);

        zero_kernel<<<1, 256>>>(bnb, 256);
        bn_stats<<<512, 128>>>();
        bn_finalize<<<1, 128>>>(gamma + i * 128, beta + i * 128);

        zero_kernel<<<(NG * DD + 255) / 256, 256>>>(pooled, NG * DD);
        node_update<<<(NN + 31) / 32, 128>>>(nbat, cur);

        small_gemm<<<(NG * 128 + 255) / 256, 256>>>(pooled, Wg + (size_t)i * 128 * 128,
                                                    bg + i * 128, ybuf, NG, 128, 128, 1, 0);
        cur ^= 1;
    }

    small_gemm<<<(NG * 64 + 255) / 256, 256>>>(ybuf, Wr1, br1, t1, NG, 128, 64, 0, 1);
    small_gemm<<<(NG * 32 + 255) / 256, 256>>>(t1, Wr2, br2, t2, NG, 64, 32, 0, 1);
    small_gemm<<<(NG * 16 + 255) / 256, 256>>>(t2, Wr3, br3, t3, NG, 32, 16, 0, 1);
    small_gemm<<<(NG * 1 + 255) / 256, 256>>>(t3, Wr4, br4, out, NG, 16, 1, 0, 1);
}

// round 13
// speedup vs baseline: 3.2167x; 1.0230x over previous
#include <cuda_runtime.h>
#include <cuda_bf16.h>
#include <math.h>
#include <stdint.h>

#define NN 50000
#define NE 400000
#define DD 128
#define NG 512

#define BSTR 40           // bf16 smem stride (conflict-free fragment reads)

// ---------------- device scratch ----------------
__device__ __align__(16) float g_x[2][NN * DD];
__device__ __align__(16) __nv_bfloat16 g_xb[NN * DD];       // bf16 mirror of current x
__device__ __align__(16) __nv_bfloat16 g_xp[NN * 96];       // padded input x (bf16)
__device__ __align__(16) __nv_bfloat16 g_e[NE * DD];        // edge embeddings (bf16)
__device__ __align__(16) __nv_bfloat16 g_eap[NE * 64];      // padded edge attrs (bf16)
__device__ __align__(16) __nv_bfloat16 g_Wnp[128 * 96];     // Wn packed n-major [n][k] (pad 96)
__device__ __align__(16) __nv_bfloat16 g_Wep[128 * 64];     // We packed n-major [n][k]
__device__ __align__(16) __nv_bfloat16 g_Wcn[512 * 128];    // node W bf16 n-major, interleaved f/s
__device__ __align__(16) __nv_bfloat16 g_Wce[256 * 128];    // edge W bf16 n-major, interleaved f/s
__device__ __align__(16) float g_ABn[NN * 512];             // interleaved [AF0,AS0,...|BF0,BS0,...]
__device__ __align__(16) float g_msg[NN * DD];
__device__ __align__(16) float g_pooled[NG * DD];
__device__ __align__(16) float g_y[NG * DD];
__device__ __align__(16) float g_t1[NG * 64];
__device__ __align__(16) float g_t2[NG * 32];
__device__ __align__(16) float g_t3[NG * 16];
__device__ __align__(16) float g_bcat_e[256];               // interleaved edge bias (f32)
__device__ __align__(16) float g_bn[512];

// ---------------- math helpers ----------------
__device__ __forceinline__ float fsp(float v) {
    return (v > 20.0f) ? v : __logf(1.0f + __expf(v));
}
__device__ __forceinline__ float fsig(float v) {
    return __fdividef(1.0f, 1.0f + __expf(-v));
}
__device__ __forceinline__ void mma_bf16(float c[4], const uint32_t a[4], const uint32_t b[2]) {
    asm volatile(
        "mma.sync.aligned.m16n8k16.row.col.f32.bf16.bf16.f32 "
        "{%0,%1,%2,%3}, {%4,%5,%6,%7}, {%8,%9}, {%0,%1,%2,%3};"
        : "+f"(c[0]), "+f"(c[1]), "+f"(c[2]), "+f"(c[3])
        : "r"(a[0]), "r"(a[1]), "r"(a[2]), "r"(a[3]), "r"(b[0]), "r"(b[1]));
}

// bf16 fragment compute over current 32-k smem chunk (As/Bs: bf16, stride BSTR)
#define BMMA_CHUNK(Asrc, Bsrc)                                                         \
    do {                                                                               \
        _Pragma("unroll")                                                              \
        for (int ks = 0; ks < 2; ks++) {                                               \
            int kk = (ks << 4) + (kc << 1);                                            \
            uint32_t a[2][4], b[8][2];                                                 \
            _Pragma("unroll")                                                          \
            for (int fm = 0; fm < 2; fm++) {                                           \
                int mb = warp_m * 32 + fm * 16 + mr;                                   \
                a[fm][0] = *(const uint32_t*)&(Asrc)[mb * BSTR + kk];                  \
                a[fm][1] = *(const uint32_t*)&(Asrc)[(mb + 8) * BSTR + kk];            \
                a[fm][2] = *(const uint32_t*)&(Asrc)[mb * BSTR + kk + 8];              \
                a[fm][3] = *(const uint32_t*)&(Asrc)[(mb + 8) * BSTR + kk + 8];        \
            }                                                                          \
            _Pragma("unroll")                                                          \
            for (int fn = 0; fn < 8; fn++) {                                           \
                int nb = warp_n * 64 + fn * 8 + mr;                                    \
                b[fn][0] = *(const uint32_t*)&(Bsrc)[nb * BSTR + kk];                  \
                b[fn][1] = *(const uint32_t*)&(Bsrc)[nb * BSTR + kk + 8];              \
            }                                                                          \
            _Pragma("unroll")                                                          \
            for (int fm = 0; fm < 2; fm++)                                             \
                _Pragma("unroll")                                                      \
                for (int fn = 0; fn < 8; fn++) mma_bf16(c[fm][fn], a[fm], b[fn]);      \
        }                                                                              \
    } while (0)

// ---------------- unified bf16 GEMM ----------------
// C = act(A[M,K]_bf16 @ Wn[Ncols,K]_bf16^T + bias)
// out_bf16=1: C is bf16. out_bf16=0: C is f32; if mirror != null also write bf16 mirror.
// grid (Ncols/128, ceil(M/128)); K % 32 == 0.
__global__ __launch_bounds__(256) void bf16_gemm(
    const __nv_bfloat16* __restrict__ A, const __nv_bfloat16* __restrict__ Wn,
    const float* __restrict__ bias, void* __restrict__ Cv,
    __nv_bfloat16* __restrict__ mirror,
    int M, int K, int Ncols, int act, int out_bf16)
{
    __shared__ __align__(16) __nv_bfloat16 As[2][128 * BSTR];
    __shared__ __align__(16) __nv_bfloat16 Bs[2][128 * BSTR];
    const int tid = threadIdx.x;
    const int lane = tid & 31, wid = tid >> 5;
    const int warp_m = wid & 3, warp_n = wid >> 2;
    const int row0 = blockIdx.y * 128;
    const int col0 = blockIdx.x * 128;
    const int mr = lane >> 2, kc = lane & 3;
    const int lr = tid >> 2, lq = (tid & 3) << 3;
    const int nch = K >> 5;

    float c[2][8][4];
#pragma unroll
    for (int i = 0; i < 2; i++)
#pragma unroll
        for (int j = 0; j < 8; j++)
#pragma unroll
            for (int q = 0; q < 4; q++) c[i][j][q] = 0.0f;

    uint4 pa[2], pb[2];
#pragma unroll
    for (int i = 0; i < 2; i++) {
        int r = lr + i * 64;
        int gr = row0 + r;
        pa[i] = (gr < M) ? *(const uint4*)(A + (size_t)gr * K + lq)
                         : make_uint4(0u, 0u, 0u, 0u);
        pb[i] = *(const uint4*)(Wn + (size_t)(col0 + r) * K + lq);
    }
#pragma unroll
    for (int i = 0; i < 2; i++) {
        int r = lr + i * 64;
        *(uint4*)&As[0][r * BSTR + lq] = pa[i];
        *(uint4*)&Bs[0][r * BSTR + lq] = pb[i];
    }
    for (int ch = 0; ch < nch; ch++) {
        int buf = ch & 1;
        if (ch + 1 < nch) {
            int k0 = (ch + 1) << 5;
#pragma unroll
            for (int i = 0; i < 2; i++) {
                int r = lr + i * 64;
                int gr = row0 + r;
                pa[i] = (gr < M) ? *(const uint4*)(A + (size_t)gr * K + k0 + lq)
                                 : make_uint4(0u, 0u, 0u, 0u);
                pb[i] = *(const uint4*)(Wn + (size_t)(col0 + r) * K + k0 + lq);
            }
        }
        __syncthreads();
        BMMA_CHUNK(As[buf], Bs[buf]);
        if (ch + 1 < nch) {
#pragma unroll
            for (int i = 0; i < 2; i++) {
                int r = lr + i * 64;
                *(uint4*)&As[buf ^ 1][r * BSTR + lq] = pa[i];
                *(uint4*)&Bs[buf ^ 1][r * BSTR + lq] = pb[i];
            }
        }
    }

#pragma unroll
    for (int fm = 0; fm < 2; fm++) {
        int rr = row0 + warp_m * 32 + fm * 16 + mr;
#pragma unroll
        for (int fn = 0; fn < 8; fn++) {
            int cc = col0 + warp_n * 64 + fn * 8 + kc * 2;
            float b0 = 0.0f, b1 = 0.0f;
            if (bias) { b0 = bias[cc]; b1 = bias[cc + 1]; }
            float v0 = c[fm][fn][0] + b0, v1 = c[fm][fn][1] + b1;
            float v2 = c[fm][fn][2] + b0, v3 = c[fm][fn][3] + b1;
            if (act) {
                v0 = fmaxf(v0, 0.0f); v1 = fmaxf(v1, 0.0f);
                v2 = fmaxf(v2, 0.0f); v3 = fmaxf(v3, 0.0f);
            }
            if (out_bf16) {
                __nv_bfloat16* C = (__nv_bfloat16*)Cv;
                if (rr < M)
                    *(__nv_bfloat162*)&C[(size_t)rr * Ncols + cc] = __floats2bfloat162_rn(v0, v1);
                if (rr + 8 < M)
                    *(__nv_bfloat162*)&C[(size_t)(rr + 8) * Ncols + cc] = __floats2bfloat162_rn(v2, v3);
            } else {
                float* C = (float*)Cv;
                if (rr < M) {
                    *(float2*)&C[(size_t)rr * Ncols + cc] = make_float2(v0, v1);
                    if (mirror)
                        *(__nv_bfloat162*)&mirror[(size_t)rr * Ncols + cc] = __floats2bfloat162_rn(v0, v1);
                }
                if (rr + 8 < M) {
                    *(float2*)&C[(size_t)(rr + 8) * Ncols + cc] = make_float2(v2, v3);
                    if (mirror)
                        *(__nv_bfloat162*)&mirror[(size_t)(rr + 8) * Ncols + cc] = __floats2bfloat162_rn(v2, v3);
                }
            }
        }
    }
}

// ---------------- fused bf16 edge GEMM + gating + scatter ----------------
// A = g_e [NE,128] bf16, W = g_Wce [256,128] bf16 n-major. grid (2, NE/128).
__global__ __launch_bounds__(256) void edge_fused(const int* __restrict__ src,
                                                  const int* __restrict__ tgt)
{
    __shared__ __align__(16) __nv_bfloat16 As[2][128 * BSTR];
    __shared__ __align__(16) __nv_bfloat16 Bs[2][128 * BSTR];
    const int tid = threadIdx.x;
    const int lane = tid & 31, wid = tid >> 5;
    const int warp_m = wid & 3, warp_n = wid >> 2;
    const int row0 = blockIdx.y * 128;
    const int col0 = blockIdx.x * 128;
    const int mr = lane >> 2, kc = lane & 3;
    const int lr = tid >> 2, lq = (tid & 3) << 3;

    int ebase = row0 + warp_m * 32 + mr;
    int s0 = src[ebase], t0 = tgt[ebase];
    int s1 = src[ebase + 8], t1 = tgt[ebase + 8];
    int s2 = src[ebase + 16], t2 = tgt[ebase + 16];
    int s3 = src[ebase + 24], t3 = tgt[ebase + 24];

    float c[2][8][4];
#pragma unroll
    for (int i = 0; i < 2; i++)
#pragma unroll
        for (int j = 0; j < 8; j++)
#pragma unroll
            for (int q = 0; q < 4; q++) c[i][j][q] = 0.0f;

    uint4 pa[2], pb[2];
#pragma unroll
    for (int i = 0; i < 2; i++) {
        int r = lr + i * 64;
        pa[i] = *(const uint4*)(g_e + (size_t)(row0 + r) * 128 + lq);
        pb[i] = *(const uint4*)(g_Wce + (size_t)(col0 + r) * 128 + lq);
    }
#pragma unroll
    for (int i = 0; i < 2; i++) {
        int r = lr + i * 64;
        *(uint4*)&As[0][r * BSTR + lq] = pa[i];
        *(uint4*)&Bs[0][r * BSTR + lq] = pb[i];
    }
#pragma unroll 1
    for (int ch = 0; ch < 4; ch++) {
        int buf = ch & 1;
        if (ch + 1 < 4) {
            int k0 = (ch + 1) << 5;
#pragma unroll
            for (int i = 0; i < 2; i++) {
                int r = lr + i * 64;
                pa[i] = *(const uint4*)(g_e + (size_t)(row0 + r) * 128 + k0 + lq);
                pb[i] = *(const uint4*)(g_Wce + (size_t)(col0 + r) * 128 + k0 + lq);
            }
        }
        __syncthreads();
        BMMA_CHUNK(As[buf], Bs[buf]);
        if (ch + 1 < 4) {
#pragma unroll
            for (int i = 0; i < 2; i++) {
                int r = lr + i * 64;
                *(uint4*)&As[buf ^ 1][r * BSTR + lq] = pa[i];
                *(uint4*)&Bs[buf ^ 1][r * BSTR + lq] = pb[i];
            }
        }
    }

    int ss[4] = {s0, s1, s2, s3};
    int tt[4] = {t0, t1, t2, t3};
#pragma unroll
    for (int fm = 0; fm < 2; fm++) {
        int i1 = fm * 2, i2 = fm * 2 + 1;
        const float2* sa1 = (const float2*)(g_ABn + (size_t)ss[i1] * 512);
        const float2* ta1 = (const float2*)(g_ABn + (size_t)tt[i1] * 512 + 256);
        const float2* sa2 = (const float2*)(g_ABn + (size_t)ss[i2] * 512);
        const float2* ta2 = (const float2*)(g_ABn + (size_t)tt[i2] * 512 + 256);
        float* m1 = g_msg + (size_t)ss[i1] * DD;
        float* m2 = g_msg + (size_t)ss[i2] * DD;
#pragma unroll
        for (int fn = 0; fn < 8; fn++) {
            int cc = col0 + warp_n * 64 + fn * 8 + kc * 2;
            int d = cc >> 1;
            float2 bi = *(const float2*)&g_bcat_e[cc];
            float2 u1 = sa1[d], v1 = ta1[d];
            float f1 = c[fm][fn][0] + bi.x + u1.x + v1.x;
            float w1 = c[fm][fn][1] + bi.y + u1.y + v1.y;
            atomicAdd(&m1[d], fsig(f1) * fsp(w1));
            float2 u2 = sa2[d], v2 = ta2[d];
            float f2 = c[fm][fn][2] + bi.x + u2.x + v2.x;
            float w2 = c[fm][fn][3] + bi.y + u2.y + v2.y;
            atomicAdd(&m2[d], fsig(f2) * fsp(w2));
        }
    }
}

// ---------------- small kernels ----------------
__global__ void zero_kernel(float* p, int n) {
    int i = blockIdx.x * blockDim.x + threadIdx.x;
    if (i < n) p[i] = 0.0f;
}

__global__ void pad_x(const float* __restrict__ x) {
    int idx = blockIdx.x * blockDim.x + threadIdx.x;
    if (idx >= NN * 96) return;
    int r = idx / 96, k = idx - r * 96;
    g_xp[idx] = __float2bfloat16(k < 92 ? x[r * 92 + k] : 0.0f);
}

__global__ void pack_Wn(const float* __restrict__ Wn) {
    int idx = blockIdx.x * blockDim.x + threadIdx.x;
    if (idx >= 128 * 96) return;
    int n = idx / 96, k = idx - n * 96;
    g_Wnp[idx] = __float2bfloat16(k < 92 ? Wn[k * 128 + n] : 0.0f);
}

__global__ void pad_ea(const float* __restrict__ ea) {
    int idx = blockIdx.x * blockDim.x + threadIdx.x;
    if (idx >= NE * 64) return;
    int e = idx >> 6, k = idx & 63;
    g_eap[idx] = __float2bfloat16(k < 41 ? ea[e * 41 + k] : 0.0f);
}

__global__ void pack_We(const float* __restrict__ We) {
    int idx = blockIdx.x * blockDim.x + threadIdx.x;
    if (idx >= 128 * 64) return;
    int n = idx >> 6, k = idx & 63;
    g_Wep[idx] = __float2bfloat16(k < 41 ? We[k * 128 + n] : 0.0f);
}

// node weights -> bf16 n-major [512 n][128 k], n interleaved f/s; n<256 top block, else mid block
__global__ void pack_node(const float* __restrict__ Wf, const float* __restrict__ Ws) {
    int idx = blockIdx.x * blockDim.x + threadIdx.x;
    if (idx >= 512 * 128) return;
    int n = idx >> 7, k = idx & 127;
    float v;
    if (n < 256) {
        int d = n >> 1;
        v = (n & 1) ? Ws[k * 128 + d] : Wf[k * 128 + d];
    } else {
        int d = (n - 256) >> 1;
        v = (n & 1) ? Ws[(128 + k) * 128 + d] : Wf[(128 + k) * 128 + d];
    }
    g_Wcn[idx] = __float2bfloat16(v);
}

__global__ void pack_edge(const float* __restrict__ Wf, const float* __restrict__ Ws,
                          const float* __restrict__ bf, const float* __restrict__ bs) {
    int idx = blockIdx.x * blockDim.x + threadIdx.x;
    if (idx >= 256 * 128) return;
    int n = idx >> 7, k = idx & 127;
    int d = n >> 1;
    float v = (n & 1) ? Ws[(256 + k) * 128 + d] : Wf[(256 + k) * 128 + d];
    g_Wce[idx] = __float2bfloat16(v);
    if (idx < 256) g_bcat_e[idx] = (idx & 1) ? bs[idx >> 1] : bf[idx >> 1];
}

__global__ void bn_stats() {
    int d = threadIdx.x;
    float s = 0.0f, ss = 0.0f;
    for (int r = blockIdx.x; r < NN; r += gridDim.x) {
        float v = g_msg[(size_t)r * DD + d];
        s += v; ss += v * v;
    }
    atomicAdd(&g_bn[d], s);
    atomicAdd(&g_bn[128 + d], ss);
}

__global__ void bn_finalize(const float* __restrict__ gamma, const float* __restrict__ beta) {
    int d = threadIdx.x;
    float mu  = g_bn[d] * (1.0f / NN);
    float var = g_bn[128 + d] * (1.0f / NN) - mu * mu;
    float rstd = rsqrtf(var + 1e-5f);
    float sc = rstd * gamma[d];
    g_bn[256 + d] = sc;
    g_bn[384 + d] = beta[d] - mu * sc;
}

__global__ __launch_bounds__(128) void node_update(const int* __restrict__ batch, int cur) {
    int d = threadIdx.x;
    int r0 = blockIdx.x * 32;
    int rend = min(r0 + 32, NN);
    const float* xin = g_x[cur];
    float* xout = g_x[cur ^ 1];
    float sc = g_bn[256 + d], sh = g_bn[384 + d];
    float acc = 0.0f;
    int curb = batch[r0];
    for (int r = r0; r < rend; r++) {
        int b = batch[r];
        if (b != curb) {
            atomicAdd(&g_pooled[(size_t)curb * DD + d], acc);
            acc = 0.0f; curb = b;
        }
        size_t idx = (size_t)r * DD + d;
        float v = fsp(xin[idx] + g_msg[idx] * sc + sh);
        xout[idx] = v;
        g_xb[idx] = __float2bfloat16(v);
        acc += v;
    }
    atomicAdd(&g_pooled[(size_t)curb * DD + d], acc);
}

__global__ void small_gemm(const float* __restrict__ A, const float* __restrict__ W,
                           const float* __restrict__ b, float* __restrict__ C,
                           int M, int K, int Nc, int accum, int act) {
    int idx = blockIdx.x * blockDim.x + threadIdx.x;
    if (idx >= M * Nc) return;
    int r = idx / Nc, c = idx % Nc;
    float s = b[c];
    for (int k = 0; k < K; k++) s = fmaf(A[r * K + k], W[k * Nc + c], s);
    if (accum) s += C[idx];
    if (act) s = fmaxf(s, 0.0f);
    C[idx] = s;
}

// ---------------- host ----------------
static float* symaddr(const void* sym) {
    void* p = nullptr;
    cudaGetSymbolAddress(&p, sym);
    return (float*)p;
}

extern "C" void kernel_launch(void* const* d_in, const int* in_sizes, int n_in,
                              void* d_out, int out_size)
{
    const float* x_in = (const float*)d_in[0];
    const float* ea   = (const float*)d_in[1];
    const int*   esrc = (const int*)d_in[2];
    const int*   etgt = (const int*)d_in[3];
    const int*   nbat = (const int*)d_in[4];
    const float* Wn   = (const float*)d_in[5];
    const float* bne  = (const float*)d_in[6];
    const float* We   = (const float*)d_in[7];
    const float* bee  = (const float*)d_in[8];
    const float* Wf   = (const float*)d_in[9];
    const float* bf   = (const float*)d_in[10];
    const float* Ws   = (const float*)d_in[11];
    const float* bs   = (const float*)d_in[12];
    int iWg = 15, ibg = 16, iga = 13, ibe = 14;
    if (in_sizes[13] == 5 * 128 * 128) { iWg = 13; ibg = 14; iga = 15; ibe = 16; }
    const float* Wg    = (const float*)d_in[iWg];
    const float* bg    = (const float*)d_in[ibg];
    const float* gamma = (const float*)d_in[iga];
    const float* beta  = (const float*)d_in[ibe];
    const float* Wr1 = (const float*)d_in[17]; const float* br1 = (const float*)d_in[18];
    const float* Wr2 = (const float*)d_in[19]; const float* br2 = (const float*)d_in[20];
    const float* Wr3 = (const float*)d_in[21]; const float* br3 = (const float*)d_in[22];
    const float* Wr4 = (const float*)d_in[23]; const float* br4 = (const float*)d_in[24];
    float* out = (float*)d_out;

    float* xbuf   = symaddr(g_x);
    float* abn    = symaddr(g_ABn);
    float* msg    = symaddr(g_msg);
    float* pooled = symaddr(g_pooled);
    float* ybuf   = symaddr(g_y);
    float* t1     = symaddr(g_t1);
    float* t2     = symaddr(g_t2);
    float* t3     = symaddr(g_t3);
    float* bnb    = symaddr(g_bn);
    __nv_bfloat16* xb   = (__nv_bfloat16*)symaddr(g_xb);
    __nv_bfloat16* xp   = (__nv_bfloat16*)symaddr(g_xp);
    __nv_bfloat16* ebuf = (__nv_bfloat16*)symaddr(g_e);
    __nv_bfloat16* eap  = (__nv_bfloat16*)symaddr(g_eap);
    __nv_bfloat16* wnp  = (__nv_bfloat16*)symaddr(g_Wnp);
    __nv_bfloat16* wep  = (__nv_bfloat16*)symaddr(g_Wep);
    __nv_bfloat16* wcn  = (__nv_bfloat16*)symaddr(g_Wcn);

    // embeddings (all bf16 tensor-core)
    pad_x<<<(NN * 96 + 255) / 256, 256>>>(x_in);
    pack_Wn<<<(128 * 96 + 255) / 256, 256>>>(Wn);
    bf16_gemm<<<dim3(1, (NN + 127) / 128), 256>>>(xp, wnp, bne, xbuf, xb, NN, 96, 128, 1, 0);
    pad_ea<<<(NE * 64) / 256, 256>>>(ea);
    pack_We<<<(128 * 64 + 255) / 256, 256>>>(We);
    bf16_gemm<<<dim3(1, NE / 128), 256>>>(eap, wep, bee, ebuf, nullptr, NE, 64, 128, 1, 1);
    zero_kernel<<<(NG * DD + 255) / 256, 256>>>(ybuf, NG * DD);

    int cur = 0;
    for (int i = 0; i < 5; i++) {
        const float* Wfi = Wf + (size_t)i * 384 * 128;
        const float* Wsi = Ws + (size_t)i * 384 * 128;
        pack_node<<<(512 * 128 + 255) / 256, 256>>>(Wfi, Wsi);
        pack_edge<<<(256 * 128 + 255) / 256, 256>>>(Wfi, Wsi, bf + i * 128, bs + i * 128);

        bf16_gemm<<<dim3(4, (NN + 127) / 128), 256>>>(
            xb, wcn, nullptr, abn, nullptr, NN, 128, 512, 0, 0);

        zero_kernel<<<(NN * DD + 255) / 256, 256>>>(msg, NN * DD);
        edge_fused<<<dim3(2, NE / 128), 256>>>(esrc, etgt);

        zero_kernel<<<1, 256>>>(bnb, 256);
        bn_stats<<<512, 128>>>();
        bn_finalize<<<1, 128>>>(gamma + i * 128, beta + i * 128);

        zero_kernel<<<(NG * DD + 255) / 256, 256>>>(pooled, NG * DD);
        node_update<<<(NN + 31) / 32, 128>>>(nbat, cur);

        small_gemm<<<(NG * 128 + 255) / 256, 256>>>(pooled, Wg + (size_t)i * 128 * 128,
                                                    bg + i * 128, ybuf, NG, 128, 128, 1, 0);
        cur ^= 1;
    }

    small_gemm<<<(NG * 64 + 255) / 256, 256>>>(ybuf, Wr1, br1, t1, NG, 128, 64, 0, 1);
    small_gemm<<<(NG * 32 + 255) / 256, 256>>>(t1, Wr2, br2, t2, NG, 64, 32, 0, 1);
    small_gemm<<<(NG * 16 + 255) / 256, 256>>>(t2, Wr3, br3, t3, NG, 32, 16, 0, 1);
    small_gemm<<<(NG * 1 + 255) / 256, 256>>>(t3, Wr4, br4, out, NG, 16, 1, 0, 1);
}

// round 15
// speedup vs baseline: 3.6129x; 1.1232x over previous
#include <cuda_runtime.h>
#include <cuda_bf16.h>
#include <math.h>
#include <stdint.h>

#define NN 50000
#define NE 400000
#define DD 128
#define NG 512

#define BSTR 40           // bf16 smem stride (conflict-free fragment reads)

// ---------------- device scratch ----------------
__device__ __align__(16) float g_x[2][NN * DD];
__device__ __align__(16) __nv_bfloat16 g_xb[NN * DD];       // bf16 mirror of current x
__device__ __align__(16) __nv_bfloat16 g_xp[NN * 96];       // padded input x (bf16)
__device__ __align__(16) __nv_bfloat16 g_e[NE * DD];        // edge embeddings (bf16)
__device__ __align__(16) __nv_bfloat16 g_eap[NE * 64];      // padded edge attrs (bf16)
__device__ __align__(16) __nv_bfloat16 g_Wnp[128 * 96];     // Wn packed n-major [n][k] (pad 96)
__device__ __align__(16) __nv_bfloat16 g_Wep[128 * 64];     // We packed n-major [n][k]
__device__ __align__(16) __nv_bfloat16 g_Wcn[512 * 128];    // node W bf16 n-major, interleaved f/s
__device__ __align__(16) __nv_bfloat16 g_Wce[256 * 128];    // edge W bf16 n-major, interleaved f/s
__device__ __align__(16) __nv_bfloat16 g_ABnh[NN * 512];    // bf16 interleaved [AF0,AS0,...|BF0,BS0,...]
__device__ __align__(16) float g_msg[NN * DD];
__device__ __align__(16) float g_pooled[NG * DD];
__device__ __align__(16) float g_y[NG * DD];
__device__ __align__(16) float g_t1[NG * 64];
__device__ __align__(16) float g_t2[NG * 32];
__device__ __align__(16) float g_t3[NG * 16];
__device__ __align__(16) float g_bcat_e[256];               // interleaved edge bias (f32)
__device__ __align__(16) float g_bn[512];

// ---------------- math helpers ----------------
__device__ __forceinline__ float fsp(float v) {
    return (v > 20.0f) ? v : __logf(1.0f + __expf(v));
}
__device__ __forceinline__ float fsig(float v) {
    return __fdividef(1.0f, 1.0f + __expf(-v));
}
__device__ __forceinline__ void mma_bf16(float c[4], const uint32_t a[4], const uint32_t b[2]) {
    asm volatile(
        "mma.sync.aligned.m16n8k16.row.col.f32.bf16.bf16.f32 "
        "{%0,%1,%2,%3}, {%4,%5,%6,%7}, {%8,%9}, {%0,%1,%2,%3};"
        : "+f"(c[0]), "+f"(c[1]), "+f"(c[2]), "+f"(c[3])
        : "r"(a[0]), "r"(a[1]), "r"(a[2]), "r"(a[3]), "r"(b[0]), "r"(b[1]));
}

// bf16 fragment compute over current 32-k smem chunk (As/Bs: bf16, stride BSTR)
#define BMMA_CHUNK(Asrc, Bsrc)                                                         \
    do {                                                                               \
        _Pragma("unroll")                                                              \
        for (int ks = 0; ks < 2; ks++) {                                               \
            int kk = (ks << 4) + (kc << 1);                                            \
            uint32_t a[2][4], b[8][2];                                                 \
            _Pragma("unroll")                                                          \
            for (int fm = 0; fm < 2; fm++) {                                           \
                int mb = warp_m * 32 + fm * 16 + mr;                                   \
                a[fm][0] = *(const uint32_t*)&(Asrc)[mb * BSTR + kk];                  \
                a[fm][1] = *(const uint32_t*)&(Asrc)[(mb + 8) * BSTR + kk];            \
                a[fm][2] = *(const uint32_t*)&(Asrc)[mb * BSTR + kk + 8];              \
                a[fm][3] = *(const uint32_t*)&(Asrc)[(mb + 8) * BSTR + kk + 8];        \
            }                                                                          \
            _Pragma("unroll")                                                          \
            for (int fn = 0; fn < 8; fn++) {                                           \
                int nb = warp_n * 64 + fn * 8 + mr;                                    \
                b[fn][0] = *(const uint32_t*)&(Bsrc)[nb * BSTR + kk];                  \
                b[fn][1] = *(const uint32_t*)&(Bsrc)[nb * BSTR + kk + 8];              \
            }                                                                          \
            _Pragma("unroll")                                                          \
            for (int fm = 0; fm < 2; fm++)                                             \
                _Pragma("unroll")                                                      \
                for (int fn = 0; fn < 8; fn++) mma_bf16(c[fm][fn], a[fm], b[fn]);      \
        }                                                                              \
    } while (0)

// ---------------- unified bf16 GEMM ----------------
// C = act(A[M,K]_bf16 @ Wn[Ncols,K]_bf16^T + bias)
// out_bf16=1: C is bf16. out_bf16=0: C is f32; if mirror != null also write bf16 mirror.
// grid (Ncols/128, ceil(M/128)); K % 32 == 0.
__global__ __launch_bounds__(256) void bf16_gemm(
    const __nv_bfloat16* __restrict__ A, const __nv_bfloat16* __restrict__ Wn,
    const float* __restrict__ bias, void* __restrict__ Cv,
    __nv_bfloat16* __restrict__ mirror,
    int M, int K, int Ncols, int act, int out_bf16)
{
    __shared__ __align__(16) __nv_bfloat16 As[2][128 * BSTR];
    __shared__ __align__(16) __nv_bfloat16 Bs[2][128 * BSTR];
    const int tid = threadIdx.x;
    const int lane = tid & 31, wid = tid >> 5;
    const int warp_m = wid & 3, warp_n = wid >> 2;
    const int row0 = blockIdx.y * 128;
    const int col0 = blockIdx.x * 128;
    const int mr = lane >> 2, kc = lane & 3;
    const int lr = tid >> 2, lq = (tid & 3) << 3;
    const int nch = K >> 5;

    float c[2][8][4];
#pragma unroll
    for (int i = 0; i < 2; i++)
#pragma unroll
        for (int j = 0; j < 8; j++)
#pragma unroll
            for (int q = 0; q < 4; q++) c[i][j][q] = 0.0f;

    uint4 pa[2], pb[2];
#pragma unroll
    for (int i = 0; i < 2; i++) {
        int r = lr + i * 64;
        int gr = row0 + r;
        pa[i] = (gr < M) ? *(const uint4*)(A + (size_t)gr * K + lq)
                         : make_uint4(0u, 0u, 0u, 0u);
        pb[i] = *(const uint4*)(Wn + (size_t)(col0 + r) * K + lq);
    }
#pragma unroll
    for (int i = 0; i < 2; i++) {
        int r = lr + i * 64;
        *(uint4*)&As[0][r * BSTR + lq] = pa[i];
        *(uint4*)&Bs[0][r * BSTR + lq] = pb[i];
    }
    for (int ch = 0; ch < nch; ch++) {
        int buf = ch & 1;
        if (ch + 1 < nch) {
            int k0 = (ch + 1) << 5;
#pragma unroll
            for (int i = 0; i < 2; i++) {
                int r = lr + i * 64;
                int gr = row0 + r;
                pa[i] = (gr < M) ? *(const uint4*)(A + (size_t)gr * K + k0 + lq)
                                 : make_uint4(0u, 0u, 0u, 0u);
                pb[i] = *(const uint4*)(Wn + (size_t)(col0 + r) * K + k0 + lq);
            }
        }
        __syncthreads();
        BMMA_CHUNK(As[buf], Bs[buf]);
        if (ch + 1 < nch) {
#pragma unroll
            for (int i = 0; i < 2; i++) {
                int r = lr + i * 64;
                *(uint4*)&As[buf ^ 1][r * BSTR + lq] = pa[i];
                *(uint4*)&Bs[buf ^ 1][r * BSTR + lq] = pb[i];
            }
        }
    }

#pragma unroll
    for (int fm = 0; fm < 2; fm++) {
        int rr = row0 + warp_m * 32 + fm * 16 + mr;
#pragma unroll
        for (int fn = 0; fn < 8; fn++) {
            int cc = col0 + warp_n * 64 + fn * 8 + kc * 2;
            float b0 = 0.0f, b1 = 0.0f;
            if (bias) { b0 = bias[cc]; b1 = bias[cc + 1]; }
            float v0 = c[fm][fn][0] + b0, v1 = c[fm][fn][1] + b1;
            float v2 = c[fm][fn][2] + b0, v3 = c[fm][fn][3] + b1;
            if (act) {
                v0 = fmaxf(v0, 0.0f); v1 = fmaxf(v1, 0.0f);
                v2 = fmaxf(v2, 0.0f); v3 = fmaxf(v3, 0.0f);
            }
            if (out_bf16) {
                __nv_bfloat16* C = (__nv_bfloat16*)Cv;
                if (rr < M)
                    *(__nv_bfloat162*)&C[(size_t)rr * Ncols + cc] = __floats2bfloat162_rn(v0, v1);
                if (rr + 8 < M)
                    *(__nv_bfloat162*)&C[(size_t)(rr + 8) * Ncols + cc] = __floats2bfloat162_rn(v2, v3);
            } else {
                float* C = (float*)Cv;
                if (rr < M) {
                    *(float2*)&C[(size_t)rr * Ncols + cc] = make_float2(v0, v1);
                    if (mirror)
                        *(__nv_bfloat162*)&mirror[(size_t)rr * Ncols + cc] = __floats2bfloat162_rn(v0, v1);
                }
                if (rr + 8 < M) {
                    *(float2*)&C[(size_t)(rr + 8) * Ncols + cc] = make_float2(v2, v3);
                    if (mirror)
                        *(__nv_bfloat162*)&mirror[(size_t)(rr + 8) * Ncols + cc] = __floats2bfloat162_rn(v2, v3);
                }
            }
        }
    }
}

// ---------------- fused bf16 edge GEMM + gating + scatter ----------------
// A = g_e [NE,128] bf16, W = g_Wce [256,128] bf16 n-major. grid (2, NE/128).
// Gathers node terms from bf16 g_ABnh (one 4B load per (f,s) pair).
__global__ __launch_bounds__(256) void edge_fused(const int* __restrict__ src,
                                                  const int* __restrict__ tgt)
{
    __shared__ __align__(16) __nv_bfloat16 As[2][128 * BSTR];
    __shared__ __align__(16) __nv_bfloat16 Bs[2][128 * BSTR];
    const int tid = threadIdx.x;
    const int lane = tid & 31, wid = tid >> 5;
    const int warp_m = wid & 3, warp_n = wid >> 2;
    const int row0 = blockIdx.y * 128;
    const int col0 = blockIdx.x * 128;
    const int mr = lane >> 2, kc = lane & 3;
    const int lr = tid >> 2, lq = (tid & 3) << 3;

    int ebase = row0 + warp_m * 32 + mr;
    int s0 = src[ebase], t0 = tgt[ebase];
    int s1 = src[ebase + 8], t1 = tgt[ebase + 8];
    int s2 = src[ebase + 16], t2 = tgt[ebase + 16];
    int s3 = src[ebase + 24], t3 = tgt[ebase + 24];

    float c[2][8][4];
#pragma unroll
    for (int i = 0; i < 2; i++)
#pragma unroll
        for (int j = 0; j < 8; j++)
#pragma unroll
            for (int q = 0; q < 4; q++) c[i][j][q] = 0.0f;

    uint4 pa[2], pb[2];
#pragma unroll
    for (int i = 0; i < 2; i++) {
        int r = lr + i * 64;
        pa[i] = *(const uint4*)(g_e + (size_t)(row0 + r) * 128 + lq);
        pb[i] = *(const uint4*)(g_Wce + (size_t)(col0 + r) * 128 + lq);
    }
#pragma unroll
    for (int i = 0; i < 2; i++) {
        int r = lr + i * 64;
        *(uint4*)&As[0][r * BSTR + lq] = pa[i];
        *(uint4*)&Bs[0][r * BSTR + lq] = pb[i];
    }
#pragma unroll 1
    for (int ch = 0; ch < 4; ch++) {
        int buf = ch & 1;
        if (ch + 1 < 4) {
            int k0 = (ch + 1) << 5;
#pragma unroll
            for (int i = 0; i < 2; i++) {
                int r = lr + i * 64;
                pa[i] = *(const uint4*)(g_e + (size_t)(row0 + r) * 128 + k0 + lq);
                pb[i] = *(const uint4*)(g_Wce + (size_t)(col0 + r) * 128 + k0 + lq);
            }
        }
        __syncthreads();
        BMMA_CHUNK(As[buf], Bs[buf]);
        if (ch + 1 < 4) {
#pragma unroll
            for (int i = 0; i < 2; i++) {
                int r = lr + i * 64;
                *(uint4*)&As[buf ^ 1][r * BSTR + lq] = pa[i];
                *(uint4*)&Bs[buf ^ 1][r * BSTR + lq] = pb[i];
            }
        }
    }

    int ss[4] = {s0, s1, s2, s3};
    int tt[4] = {t0, t1, t2, t3};
#pragma unroll
    for (int fm = 0; fm < 2; fm++) {
        int i1 = fm * 2, i2 = fm * 2 + 1;
        const __nv_bfloat162* sa1 = (const __nv_bfloat162*)(g_ABnh + (size_t)ss[i1] * 512);
        const __nv_bfloat162* ta1 = (const __nv_bfloat162*)(g_ABnh + (size_t)tt[i1] * 512 + 256);
        const __nv_bfloat162* sa2 = (const __nv_bfloat162*)(g_ABnh + (size_t)ss[i2] * 512);
        const __nv_bfloat162* ta2 = (const __nv_bfloat162*)(g_ABnh + (size_t)tt[i2] * 512 + 256);
        float* m1 = g_msg + (size_t)ss[i1] * DD;
        float* m2 = g_msg + (size_t)ss[i2] * DD;
#pragma unroll
        for (int fn = 0; fn < 8; fn++) {
            int cc = col0 + warp_n * 64 + fn * 8 + kc * 2;
            int d = cc >> 1;
            float2 bi = *(const float2*)&g_bcat_e[cc];
            float2 u1 = __bfloat1622float2(sa1[d]);
            float2 v1 = __bfloat1622float2(ta1[d]);
            float f1 = c[fm][fn][0] + bi.x + u1.x + v1.x;
            float w1 = c[fm][fn][1] + bi.y + u1.y + v1.y;
            atomicAdd(&m1[d], fsig(f1) * fsp(w1));
            float2 u2 = __bfloat1622float2(sa2[d]);
            float2 v2 = __bfloat1622float2(ta2[d]);
            float f2 = c[fm][fn][2] + bi.x + u2.x + v2.x;
            float w2 = c[fm][fn][3] + bi.y + u2.y + v2.y;
            atomicAdd(&m2[d], fsig(f2) * fsp(w2));
        }
    }
}

// ---------------- small kernels ----------------
__global__ void zero_kernel(float* p, int n) {
    int i = blockIdx.x * blockDim.x + threadIdx.x;
    if (i < n) p[i] = 0.0f;
}

__global__ void pad_x(const float* __restrict__ x) {
    int idx = blockIdx.x * blockDim.x + threadIdx.x;
    if (idx >= NN * 96) return;
    int r = idx / 96, k = idx - r * 96;
    g_xp[idx] = __float2bfloat16(k < 92 ? x[r * 92 + k] : 0.0f);
}

__global__ void pack_Wn(const float* __restrict__ Wn) {
    int idx = blockIdx.x * blockDim.x + threadIdx.x;
    if (idx >= 128 * 96) return;
    int n = idx / 96, k = idx - n * 96;
    g_Wnp[idx] = __float2bfloat16(k < 92 ? Wn[k * 128 + n] : 0.0f);
}

__global__ void pad_ea(const float* __restrict__ ea) {
    int idx = blockIdx.x * blockDim.x + threadIdx.x;
    if (idx >= NE * 64) return;
    int e = idx >> 6, k = idx & 63;
    g_eap[idx] = __float2bfloat16(k < 41 ? ea[e * 41 + k] : 0.0f);
}

__global__ void pack_We(const float* __restrict__ We) {
    int idx = blockIdx.x * blockDim.x + threadIdx.x;
    if (idx >= 128 * 64) return;
    int n = idx >> 6, k = idx & 63;
    g_Wep[idx] = __float2bfloat16(k < 41 ? We[k * 128 + n] : 0.0f);
}

// node weights -> bf16 n-major [512 n][128 k], n interleaved f/s; n<256 top block, else mid block
__global__ void pack_node(const float* __restrict__ Wf, const float* __restrict__ Ws) {
    int idx = blockIdx.x * blockDim.x + threadIdx.x;
    if (idx >= 512 * 128) return;
    int n = idx >> 7, k = idx & 127;
    float v;
    if (n < 256) {
        int d = n >> 1;
        v = (n & 1) ? Ws[k * 128 + d] : Wf[k * 128 + d];
    } else {
        int d = (n - 256) >> 1;
        v = (n & 1) ? Ws[(128 + k) * 128 + d] : Wf[(128 + k) * 128 + d];
    }
    g_Wcn[idx] = __float2bfloat16(v);
}

__global__ void pack_edge(const float* __restrict__ Wf, const float* __restrict__ Ws,
                          const float* __restrict__ bf, const float* __restrict__ bs) {
    int idx = blockIdx.x * blockDim.x + threadIdx.x;
    if (idx >= 256 * 128) return;
    int n = idx >> 7, k = idx & 127;
    int d = n >> 1;
    float v = (n & 1) ? Ws[(256 + k) * 128 + d] : Wf[(256 + k) * 128 + d];
    g_Wce[idx] = __float2bfloat16(v);
    if (idx < 256) g_bcat_e[idx] = (idx & 1) ? bs[idx >> 1] : bf[idx >> 1];
}

__global__ void bn_stats() {
    int d = threadIdx.x;
    float s = 0.0f, ss = 0.0f;
    for (int r = blockIdx.x; r < NN; r += gridDim.x) {
        float v = g_msg[(size_t)r * DD + d];
        s += v; ss += v * v;
    }
    atomicAdd(&g_bn[d], s);
    atomicAdd(&g_bn[128 + d], ss);
}

__global__ void bn_finalize(const float* __restrict__ gamma, const float* __restrict__ beta) {
    int d = threadIdx.x;
    float mu  = g_bn[d] * (1.0f / NN);
    float var = g_bn[128 + d] * (1.0f / NN) - mu * mu;
    float rstd = rsqrtf(var + 1e-5f);
    float sc = rstd * gamma[d];
    g_bn[256 + d] = sc;
    g_bn[384 + d] = beta[d] - mu * sc;
}

__global__ __launch_bounds__(128) void node_update(const int* __restrict__ batch, int cur) {
    int d = threadIdx.x;
    int r0 = blockIdx.x * 32;
    int rend = min(r0 + 32, NN);
    const float* xin = g_x[cur];
    float* xout = g_x[cur ^ 1];
    float sc = g_bn[256 + d], sh = g_bn[384 + d];
    float acc = 0.0f;
    int curb = batch[r0];
    for (int r = r0; r < rend; r++) {
        int b = batch[r];
        if (b != curb) {
            atomicAdd(&g_pooled[(size_t)curb * DD + d], acc);
            acc = 0.0f; curb = b;
        }
        size_t idx = (size_t)r * DD + d;
        float v = fsp(xin[idx] + g_msg[idx] * sc + sh);
        xout[idx] = v;
        g_xb[idx] = __float2bfloat16(v);
        acc += v;
    }
    atomicAdd(&g_pooled[(size_t)curb * DD + d], acc);
}

__global__ void small_gemm(const float* __restrict__ A, const float* __restrict__ W,
                           const float* __restrict__ b, float* __restrict__ C,
                           int M, int K, int Nc, int accum, int act) {
    int idx = blockIdx.x * blockDim.x + threadIdx.x;
    if (idx >= M * Nc) return;
    int r = idx / Nc, c = idx % Nc;
    float s = b[c];
    for (int k = 0; k < K; k++) s = fmaf(A[r * K + k], W[k * Nc + c], s);
    if (accum) s += C[idx];
    if (act) s = fmaxf(s, 0.0f);
    C[idx] = s;
}

// ---------------- host ----------------
static float* symaddr(const void* sym) {
    void* p = nullptr;
    cudaGetSymbolAddress(&p, sym);
    return (float*)p;
}

extern "C" void kernel_launch(void* const* d_in, const int* in_sizes, int n_in,
                              void* d_out, int out_size)
{
    const float* x_in = (const float*)d_in[0];
    const float* ea   = (const float*)d_in[1];
    const int*   esrc = (const int*)d_in[2];
    const int*   etgt = (const int*)d_in[3];
    const int*   nbat = (const int*)d_in[4];
    const float* Wn   = (const float*)d_in[5];
    const float* bne  = (const float*)d_in[6];
    const float* We   = (const float*)d_in[7];
    const float* bee  = (const float*)d_in[8];
    const float* Wf   = (const float*)d_in[9];
    const float* bf   = (const float*)d_in[10];
    const float* Ws   = (const float*)d_in[11];
    const float* bs   = (const float*)d_in[12];
    int iWg = 15, ibg = 16, iga = 13, ibe = 14;
    if (in_sizes[13] == 5 * 128 * 128) { iWg = 13; ibg = 14; iga = 15; ibe = 16; }
    const float* Wg    = (const float*)d_in[iWg];
    const float* bg    = (const float*)d_in[ibg];
    const float* gamma = (const float*)d_in[iga];
    const float* beta  = (const float*)d_in[ibe];
    const float* Wr1 = (const float*)d_in[17]; const float* br1 = (const float*)d_in[18];
    const float* Wr2 = (const float*)d_in[19]; const float* br2 = (const float*)d_in[20];
    const float* Wr3 = (const float*)d_in[21]; const float* br3 = (const float*)d_in[22];
    const float* Wr4 = (const float*)d_in[23]; const float* br4 = (const float*)d_in[24];
    float* out = (float*)d_out;

    float* xbuf   = symaddr(g_x);
    float* msg    = symaddr(g_msg);
    float* pooled = symaddr(g_pooled);
    float* ybuf   = symaddr(g_y);
    float* t1     = symaddr(g_t1);
    float* t2     = symaddr(g_t2);
    float* t3     = symaddr(g_t3);
    float* bnb    = symaddr(g_bn);
    __nv_bfloat16* xb   = (__nv_bfloat16*)symaddr(g_xb);
    __nv_bfloat16* xp   = (__nv_bfloat16*)symaddr(g_xp);
    __nv_bfloat16* ebuf = (__nv_bfloat16*)symaddr(g_e);
    __nv_bfloat16* eap  = (__nv_bfloat16*)symaddr(g_eap);
    __nv_bfloat16* wnp  = (__nv_bfloat16*)symaddr(g_Wnp);
    __nv_bfloat16* wep  = (__nv_bfloat16*)symaddr(g_Wep);
    __nv_bfloat16* wcn  = (__nv_bfloat16*)symaddr(g_Wcn);
    __nv_bfloat16* abnh = (__nv_bfloat16*)symaddr(g_ABnh);

    // embeddings (all bf16 tensor-core)
    pad_x<<<(NN * 96 + 255) / 256, 256>>>(x_in);
    pack_Wn<<<(128 * 96 + 255) / 256, 256>>>(Wn);
    bf16_gemm<<<dim3(1, (NN + 127) / 128), 256>>>(xp, wnp, bne, xbuf, xb, NN, 96, 128, 1, 0);
    pad_ea<<<(NE * 64) / 256, 256>>>(ea);
    pack_We<<<(128 * 64 + 255) / 256, 256>>>(We);
    bf16_gemm<<<dim3(1, NE / 128), 256>>>(eap, wep, bee, ebuf, nullptr, NE, 64, 128, 1, 1);
    zero_kernel<<<(NG * DD + 255) / 256, 256>>>(ybuf, NG * DD);

    int cur = 0;
    for (int i = 0; i < 5; i++) {
        const float* Wfi = Wf + (size_t)i * 384 * 128;
        const float* Wsi = Ws + (size_t)i * 384 * 128;
        pack_node<<<(512 * 128 + 255) / 256, 256>>>(Wfi, Wsi);
        pack_edge<<<(256 * 128 + 255) / 256, 256>>>(Wfi, Wsi, bf + i * 128, bs + i * 128);

        // node GEMM -> bf16 ABn (halved write + gather traffic)
        bf16_gemm<<<dim3(4, (NN + 127) / 128), 256>>>(
            xb, wcn, nullptr, abnh, nullptr, NN, 128, 512, 0, 1);

        zero_kernel<<<(NN * DD + 255) / 256, 256>>>(msg, NN * DD);
        edge_fused<<<dim3(2, NE / 128), 256>>>(esrc, etgt);

        zero_kernel<<<1, 256>>>(bnb, 256);
        bn_stats<<<512, 128>>>();
        bn_finalize<<<1, 128>>>(gamma + i * 128, beta + i * 128);

        zero_kernel<<<(NG * DD + 255) / 256, 256>>>(pooled, NG * DD);
        node_update<<<(NN + 31) / 32, 128>>>(nbat, cur);

        small_gemm<<<(NG * 128 + 255) / 256, 256>>>(pooled, Wg + (size_t)i * 128 * 128,
                                                    bg + i * 128, ybuf, NG, 128, 128, 1, 0);
        cur ^= 1;
    }

    small_gemm<<<(NG * 64 + 255) / 256, 256>>>(ybuf, Wr1, br1, t1, NG, 128, 64, 0, 1);
    small_gemm<<<(NG * 32 + 255) / 256, 256>>>(t1, Wr2, br2, t2, NG, 64, 32, 0, 1);
    small_gemm<<<(NG * 16 + 255) / 256, 256>>>(t2, Wr3, br3, t3, NG, 32, 16, 0, 1);
    small_gemm<<<(NG * 1 + 255) / 256, 256>>>(t3, Wr4, br4, out, NG, 16, 1, 0, 1);
}